// round 6
// baseline (speedup 1.0000x reference)
#include <cuda_runtime.h>
#include <cuda_bf16.h>
#include <math.h>
#include <stdint.h>

#define BSZ 2
#define LSZ 1024
#define DM 768
#define NL 4
#define DI 1536
#define DS 16
#define DTR 48
#define XPN 80          // DTR + 2*DS
#define ROWS (BSZ*LSZ)  // 2048

// extended-K sizes (3 segments for bf16-split exact GEMM)
#define KE_IN   (3*DM)     // 2304
#define KE_BIG  (3*DI)     // 4608
#define KE_DT   (3*64)     // 192

#define STAGES 4
#define GSMEM (STAGES*16384)   // 64KB dynamic smem

// ---------------- scratch (device globals; no allocation allowed) ----------
__device__ float g_resid[ROWS * DM];
__device__ float g_xz[ROWS * 2 * DI];
__device__ float g_xdbl[ROWS * XPN];
__device__ float g_dT[ROWS * DI];    // delta transposed [c][l]
__device__ float g_xcT[ROWS * DI];   // conv output transposed [c][l]
__device__ float g_zT[ROWS * DI];    // gate transposed [c][l]
__device__ float g_bmT[BSZ * DS * LSZ];
__device__ float g_cmT[BSZ * DS * LSZ];
__device__ __nv_bfloat16 g_aext[ROWS * KE_BIG];          // activation ext (reused)
__device__ __nv_bfloat16 g_wi[NL][(2 * DI) * KE_IN];     // in_proj ext
__device__ __nv_bfloat16 g_wo[NL][DM * KE_BIG];          // out_proj ext
__device__ __nv_bfloat16 g_wx[NL][128 * KE_BIG];         // x_proj ext (N padded 128)
__device__ __nv_bfloat16 g_wd[NL][DI * KE_DT];           // dt ext

// ---------------- small helpers ----------------
__device__ __forceinline__ uint32_t smem_to_u32(const void* p) {
    uint32_t a;
    asm("{ .reg .u64 t; cvta.to.shared.u64 t, %1; cvt.u32.u64 %0, t; }"
        : "=r"(a) : "l"(p));
    return a;
}
__device__ __forceinline__ void cp16(uint32_t dst, const void* src) {
    asm volatile("cp.async.cg.shared.global [%0], [%1], 16;" :: "r"(dst), "l"(src));
}
__device__ __forceinline__ void ldsm4(uint32_t* r, uint32_t addr) {
    asm volatile("ldmatrix.sync.aligned.m8n8.x4.shared.b16 {%0,%1,%2,%3}, [%4];"
        : "=r"(r[0]), "=r"(r[1]), "=r"(r[2]), "=r"(r[3]) : "r"(addr));
}
__device__ __forceinline__ void mma16816(float* c, const uint32_t* a, const uint32_t* b) {
    asm volatile("mma.sync.aligned.m16n8k16.row.col.f32.bf16.bf16.f32 "
        "{%0,%1,%2,%3}, {%4,%5,%6,%7}, {%8,%9}, {%0,%1,%2,%3};"
        : "+f"(c[0]), "+f"(c[1]), "+f"(c[2]), "+f"(c[3])
        : "r"(a[0]), "r"(a[1]), "r"(a[2]), "r"(a[3]), "r"(b[0]), "r"(b[1]));
}
__device__ __forceinline__ void bsplit(float v, __nv_bfloat16& h, __nv_bfloat16& l) {
    h = __float2bfloat16(v);
    l = __float2bfloat16(v - __bfloat162float(h));
}
__device__ __forceinline__ float softplus_f(float v) {
    return fmaxf(v, 0.f) + __logf(1.f + __expf(-fabsf(v)));
}

__device__ __forceinline__ float block_sum(float v) {
    __shared__ float sh[8];
    __syncthreads();
#pragma unroll
    for (int o = 16; o; o >>= 1) v += __shfl_xor_sync(0xffffffffu, v, o);
    if ((threadIdx.x & 31) == 0) sh[threadIdx.x >> 5] = v;
    __syncthreads();
    if (threadIdx.x < 32) {
        float t = (threadIdx.x < (blockDim.x >> 5)) ? sh[threadIdx.x] : 0.f;
#pragma unroll
        for (int o = 4; o; o >>= 1) t += __shfl_xor_sync(0xffffffffu, t, o);
        if (threadIdx.x == 0) sh[0] = t;
    }
    __syncthreads();
    return sh[0];
}

// ---------------- embedding gather ----------------
__global__ void embed_k(const int* __restrict__ seq, const float* __restrict__ emb,
                        float* __restrict__ resid) {
    int i = blockIdx.x * blockDim.x + threadIdx.x;
    if (i >= ROWS * (DM / 4)) return;
    int row = i / (DM / 4), c4 = i % (DM / 4);
    int tok = seq[row];
    reinterpret_cast<float4*>(resid)[(size_t)row * (DM / 4) + c4] =
        reinterpret_cast<const float4*>(emb)[(size_t)tok * (DM / 4) + c4];
}

// ---------------- rmsnorm: writes ext layout (Kext=2304) -------------------
__global__ void rmsnorm_k(const float* __restrict__ x, const float* __restrict__ w,
                          __nv_bfloat16* __restrict__ ae) {
    int row = blockIdx.x;
    const float* xr = x + (size_t)row * DM;
    float s = 0.f;
    for (int c = threadIdx.x; c < DM; c += blockDim.x) { float v = xr[c]; s += v * v; }
    s = block_sum(s);
    float inv = rsqrtf(s / (float)DM + 1e-5f);
    __nv_bfloat16* ar = ae + (size_t)row * KE_IN;
    for (int c = threadIdx.x; c < DM; c += blockDim.x) {
        float v = xr[c] * inv * w[c];
        __nv_bfloat16 h, l; bsplit(v, h, l);
        ar[c] = h; ar[c + DM] = h; ar[c + 2 * DM] = l;
    }
}

// ---------------- weight prep: fp32 [N,Ksrc] -> ext bf16 [Npad, 3*Kpad] ----
__global__ void wprep_k(const float* __restrict__ w, __nv_bfloat16* __restrict__ e,
                        int N, int Npad, int Ksrc, int Kpad) {
    int i = blockIdx.x * blockDim.x + threadIdx.x;
    if (i >= Npad * Kpad) return;
    int n = i / Kpad, k = i - n * Kpad;
    float v = (n < N && k < Ksrc) ? w[(size_t)n * Ksrc + k] : 0.f;
    __nv_bfloat16 h, l; bsplit(v, h, l);
    __nv_bfloat16* er = e + (size_t)n * (3 * Kpad);
    er[k] = h; er[k + Kpad] = l; er[k + 2 * Kpad] = h;
}

// ---------------- dt A prep: xdbl[:, :48] -> ext [ROWS, 192] ---------------
__global__ void dtprep_k(const float* __restrict__ xdbl, __nv_bfloat16* __restrict__ ae) {
    int i = blockIdx.x * blockDim.x + threadIdx.x;
    if (i >= ROWS * 64) return;
    int r = i >> 6, k = i & 63;
    float v = (k < DTR) ? xdbl[(size_t)r * XPN + k] : 0.f;
    __nv_bfloat16 h, l; bsplit(v, h, l);
    __nv_bfloat16* ar = ae + (size_t)r * KE_DT;
    ar[k] = h; ar[k + 64] = h; ar[k + 128] = l;
}

// ---------------- B/C transpose: xdbl[:, 48:80] -> bmT/cmT [b*DS+s][l] -----
__global__ void transp_bc_k(const float* __restrict__ xdbl,
                            float* __restrict__ bmT, float* __restrict__ cmT) {
    int i = blockIdx.x * blockDim.x + threadIdx.x;
    if (i >= ROWS * 2 * DS) return;
    int r = i / (2 * DS), j = i - r * (2 * DS);
    float v = xdbl[(size_t)r * XPN + DTR + j];
    int b = r >> 10, l = r & (LSZ - 1);
    if (j < DS) bmT[((b * DS + j) << 10) + l] = v;
    else        cmT[((b * DS + j - DS) << 10) + l] = v;
}

// ---------------- depthwise conv + silu: writes xcT, zT, ext ---------------
__global__ void conv_silu_k(const float* __restrict__ xz, const float* __restrict__ cw,
                            const float* __restrict__ cb, float* __restrict__ xcT,
                            float* __restrict__ zT, __nv_bfloat16* __restrict__ ae) {
    int i = blockIdx.x * blockDim.x + threadIdx.x;
    if (i >= ROWS * DI) return;
    int d = i % DI;
    int row = i / DI;
    int l = row & (LSZ - 1);
    float acc = cb[d];
#pragma unroll
    for (int k = 0; k < 4; k++) {
        int l2 = l + k - 3;
        if (l2 >= 0)
            acc += xz[(size_t)(row + k - 3) * (2 * DI) + d] * cw[d * 4 + k];
    }
    acc = acc / (1.f + __expf(-acc));
    size_t tidx = ((size_t)(row >> 10) * DI + d) * LSZ + l;   // [c][l]
    xcT[tidx] = acc;
    zT[tidx] = xz[(size_t)row * (2 * DI) + DI + d];
    __nv_bfloat16 h, lo; bsplit(acc, h, lo);
    __nv_bfloat16* ar = ae + (size_t)row * KE_BIG;
    ar[d] = h; ar[d + DI] = h; ar[d + 2 * DI] = lo;
}

// ---------------- bf16 tensor-core GEMM: C = Aext @ Wext^T -----------------
// CTA tile 128x128x32, 8 warps (4x2), 4-stage cp.async pipeline.
// EPI: 0 = store, 1 = softplus(acc+bias[n]) stored TRANSPOSED [c][l],
//      3 = atomicAdd (guard n < N)
template <int EPI>
__global__ void __launch_bounds__(256) gemm_bf(
    const __nv_bfloat16* __restrict__ Aext, const __nv_bfloat16* __restrict__ Wext,
    float* __restrict__ C, const float* __restrict__ bias,
    int Kext, int kIters, int N, int ldc) {
    extern __shared__ __align__(16) uint8_t smem[];
    int tid = threadIdx.x;
    int wid = tid >> 5, lane = tid & 31;
    int m0 = blockIdx.y * 128, n0 = blockIdx.x * 128;
    int kbase = blockIdx.z * kIters * 32;

    int warp_m = wid & 3, warp_n = wid >> 2;   // 4 x 2 warp grid

    int lrow = tid >> 2;       // 0..63
    int lch = tid & 3;         // 0..3
    const char* Ag = (const char*)(Aext + (size_t)(m0 + lrow) * Kext + kbase + lch * 8);
    const char* Bg = (const char*)(Wext + (size_t)(n0 + lrow) * Kext + kbase + lch * 8);
    size_t rstep = (size_t)64 * Kext * 2;
    uint32_t su = smem_to_u32(smem);
    uint32_t dst0 = (uint32_t)(lrow * 64 + ((lch ^ ((lrow >> 1) & 3)) * 16));

    float acc[2][8][4];
#pragma unroll
    for (int a = 0; a < 2; a++)
#pragma unroll
        for (int b = 0; b < 8; b++)
#pragma unroll
            for (int c = 0; c < 4; c++) acc[a][b][c] = 0.f;

#define LOAD_STAGE(st, kt) do { \
    if ((kt) < kIters) { \
        uint32_t _o = (uint32_t)(st) * 16384 + dst0; \
        size_t _g = (size_t)(kt) * 64; \
        cp16(su + _o, Ag + _g); \
        cp16(su + _o + 4096, Ag + rstep + _g); \
        cp16(su + _o + 8192, Bg + _g); \
        cp16(su + _o + 12288, Bg + rstep + _g); \
    } \
    asm volatile("cp.async.commit_group;"); \
} while (0)

#pragma unroll
    for (int s = 0; s < STAGES - 1; s++) LOAD_STAGE(s, s);

    for (int kt = 0; kt < kIters; kt++) {
        asm volatile("cp.async.wait_group %0;" :: "n"(STAGES - 2) : "memory");
        __syncthreads();
        LOAD_STAGE((kt + STAGES - 1) & (STAGES - 1), kt + STAGES - 1);
        int st = kt & (STAGES - 1);
        uint32_t baseA = su + st * 16384;
        uint32_t baseB = baseA + 8192;
#pragma unroll
        for (int ks = 0; ks < 2; ks++) {
            int lr16 = lane & 15;
            int ach = ks * 2 + (lane >> 4);
            uint32_t afr[2][4];
#pragma unroll
            for (int mf = 0; mf < 2; mf++) {
                int r = warp_m * 32 + mf * 16 + lr16;
                ldsm4(afr[mf], baseA + r * 64 + ((ach ^ ((r >> 1) & 3)) * 16));
            }
#pragma unroll
            for (int np = 0; np < 4; np++) {
                int r = warp_n * 64 + np * 16 + lr16;
                uint32_t bfr[4];
                ldsm4(bfr, baseB + r * 64 + ((ach ^ ((r >> 1) & 3)) * 16));
                uint32_t b0[2] = {bfr[0], bfr[2]};
                uint32_t b1[2] = {bfr[1], bfr[3]};
#pragma unroll
                for (int mf = 0; mf < 2; mf++) {
                    mma16816(acc[mf][np * 2], afr[mf], b0);
                    mma16816(acc[mf][np * 2 + 1], afr[mf], b1);
                }
            }
        }
    }

    int trow = lane >> 2, tc2 = (lane & 3) * 2;
#pragma unroll
    for (int mf = 0; mf < 2; mf++) {
#pragma unroll
        for (int nf = 0; nf < 8; nf++) {
            int n = n0 + warp_n * 64 + nf * 8 + tc2;
            int m = m0 + warp_m * 32 + mf * 16 + trow;
#pragma unroll
            for (int hh = 0; hh < 2; hh++) {
                float v0 = acc[mf][nf][hh * 2];
                float v1 = acc[mf][nf][hh * 2 + 1];
                int mr = m + hh * 8;
                if (EPI == 1) {
                    // store transposed into dT[(b*DI + n)][l]
                    v0 = softplus_f(v0 + bias[n]);
                    v1 = softplus_f(v1 + bias[n + 1]);
                    size_t base = ((size_t)(mr >> 10) * DI) << 10;
                    size_t lofs = (size_t)(mr & (LSZ - 1));
                    C[base + ((size_t)n << 10) + lofs] = v0;
                    C[base + ((size_t)(n + 1) << 10) + lofs] = v1;
                } else if (EPI == 3) {
                    if (n < N)     atomicAdd(&C[(size_t)mr * ldc + n], v0);
                    if (n + 1 < N) atomicAdd(&C[(size_t)mr * ldc + n + 1], v1);
                } else {
                    *reinterpret_cast<float2*>(&C[(size_t)mr * ldc + n]) =
                        make_float2(v0, v1);
                }
            }
        }
    }
#undef LOAD_STAGE
}

// ---------------- selective scan: transposed streams, float4 x ring(2) -----
__global__ void __launch_bounds__(256) scan_k(
    const float* __restrict__ dT, const float* __restrict__ xcT,
    const float* __restrict__ zT, const float* __restrict__ bmT,
    const float* __restrict__ cmT, const float* __restrict__ A_log,
    const float* __restrict__ dski, __nv_bfloat16* __restrict__ ye) {
    int warp = (blockIdx.x * blockDim.x + threadIdx.x) >> 5;
    int lane = threadIdx.x & 31;
    int half = lane >> 4;
    int s = lane & 15;
    int c = warp * 2 + half;
    if (c >= BSZ * DI) return;
    int b = c / DI;
    int d = c % DI;

    float As = -__expf(A_log[d * DS + s]);
    float dsk = dski[d];
    const float4* dp = (const float4*)(dT + ((size_t)c << 10));
    const float4* up = (const float4*)(xcT + ((size_t)c << 10));
    const float4* zp = (const float4*)(zT + ((size_t)c << 10));
    const float4* bp = (const float4*)(bmT + (((size_t)b * DS + s) << 10));
    const float4* cp = (const float4*)(cmT + (((size_t)b * DS + s) << 10));
    __nv_bfloat16* yr = ye + (size_t)b * LSZ * KE_BIG + d;

    float4 dr[2], ur[2], zr[2], br[2], cr[2];
    dr[0] = dp[0]; ur[0] = up[0]; zr[0] = zp[0]; br[0] = bp[0]; cr[0] = cp[0];
    dr[1] = dp[1]; ur[1] = up[1]; zr[1] = zp[1]; br[1] = bp[1]; cr[1] = cp[1];

    float h = 0.f;
    float praw = 0.f, ppart = 0.f;    // raw p (step l-1), partial p (step l-2)
    float u1 = 0.f, z1 = 0.f, u2 = 0.f, z2 = 0.f;
    const int NG = LSZ / 4;

    for (int g = 0; g < NG; g++) {
        int buf = g & 1;
        float4 dv = dr[buf], uv = ur[buf], zv = zr[buf], bv = br[buf], cv = cr[buf];
        if (g + 2 < NG) {
            dr[buf] = dp[g + 2]; ur[buf] = up[g + 2]; zr[buf] = zp[g + 2];
            br[buf] = bp[g + 2]; cr[buf] = cp[g + 2];
        }
        const float* da = (const float*)&dv;
        const float* ua = (const float*)&uv;
        const float* za = (const float*)&zv;
        const float* ba = (const float*)&bv;
        const float* ca = (const float*)&cv;
#pragma unroll
        for (int j = 0; j < 4; j++) {
            int l = g * 4 + j;
            float dl = da[j], u = ua[j], z = za[j], bm = ba[j], cm = ca[j];
            float a8 = __shfl_xor_sync(0xffffffffu, praw, 8);
            float b2 = __shfl_xor_sync(0xffffffffu, ppart, 2);
            float dA = __expf(dl * As);
            float dlu = dl * u;
            praw += a8;
            ppart += b2;
            float a4 = __shfl_xor_sync(0xffffffffu, praw, 4);
            float b1 = __shfl_xor_sync(0xffffffffu, ppart, 1);
            h = dA * h + dlu * bm;
            float pnew = h * cm;
            praw += a4;
            ppart += b1;
            if (l >= 2 && s == 0) {
                float yv = (ppart + u2 * dsk) * (z2 / (1.f + __expf(-z2)));
                __nv_bfloat16 hh, ll; bsplit(yv, hh, ll);
                __nv_bfloat16* yp = yr + (size_t)(l - 2) * KE_BIG;
                yp[0] = hh; yp[DI] = hh; yp[2 * DI] = ll;
            }
            ppart = praw; praw = pnew;
            u2 = u1; z2 = z1; u1 = u; z1 = z;
        }
    }
    // drain
    ppart += __shfl_xor_sync(0xffffffffu, ppart, 2);
    ppart += __shfl_xor_sync(0xffffffffu, ppart, 1);
    praw += __shfl_xor_sync(0xffffffffu, praw, 8);
    praw += __shfl_xor_sync(0xffffffffu, praw, 4);
    praw += __shfl_xor_sync(0xffffffffu, praw, 2);
    praw += __shfl_xor_sync(0xffffffffu, praw, 1);
    if (s == 0) {
        float yv = (ppart + u2 * dsk) * (z2 / (1.f + __expf(-z2)));
        __nv_bfloat16 hh, ll; bsplit(yv, hh, ll);
        __nv_bfloat16* yp = yr + (size_t)(LSZ - 2) * KE_BIG;
        yp[0] = hh; yp[DI] = hh; yp[2 * DI] = ll;
        yv = (praw + u1 * dsk) * (z1 / (1.f + __expf(-z1)));
        bsplit(yv, hh, ll);
        yp = yr + (size_t)(LSZ - 1) * KE_BIG;
        yp[0] = hh; yp[DI] = hh; yp[2 * DI] = ll;
    }
}

// ---------------- final: last-token rmsnorm ----------------
__global__ void final_k(const float* __restrict__ resid, const float* __restrict__ nw,
                        const int* __restrict__ mask, float* __restrict__ out) {
    int b = blockIdx.x;
    float ms = 0.f;
    for (int i = threadIdx.x; i < LSZ; i += blockDim.x) ms += (float)mask[b * LSZ + i];
    ms = block_sum(ms);
    int last = (int)(ms + 0.5f) - 1;
    const float* xr = resid + ((size_t)b * LSZ + last) * DM;
    float sacc = 0.f;
    for (int cidx = threadIdx.x; cidx < DM; cidx += blockDim.x) {
        float v = xr[cidx];
        sacc += v * v;
    }
    sacc = block_sum(sacc);
    float inv = rsqrtf(sacc / (float)DM + 1e-5f);
    for (int cidx = threadIdx.x; cidx < DM; cidx += blockDim.x)
        out[b * DM + cidx] = xr[cidx] * inv * nw[cidx];
}

// ---------------- driver ----------------
extern "C" void kernel_launch(void* const* d_in, const int* in_sizes, int n_in,
                              void* d_out, int out_size) {
    const int*   seq       = (const int*)d_in[0];
    const int*   mask      = (const int*)d_in[1];
    const float* emb       = (const float*)d_in[2];
    const float* norm_w    = (const float*)d_in[3];
    const float* in_proj_w = (const float*)d_in[4];
    const float* conv_w    = (const float*)d_in[5];
    const float* conv_b    = (const float*)d_in[6];
    const float* x_proj_w  = (const float*)d_in[7];
    const float* dt_w      = (const float*)d_in[8];
    const float* dt_b      = (const float*)d_in[9];
    const float* A_log     = (const float*)d_in[10];
    const float* D_skip    = (const float*)d_in[11];
    const float* out_w     = (const float*)d_in[12];
    const float* normf_w   = (const float*)d_in[13];

    float *resid, *xz, *xdbl, *dT, *xcT, *zT, *bmT, *cmT;
    __nv_bfloat16 *ae;
    cudaGetSymbolAddress((void**)&resid, g_resid);
    cudaGetSymbolAddress((void**)&xz,    g_xz);
    cudaGetSymbolAddress((void**)&xdbl,  g_xdbl);
    cudaGetSymbolAddress((void**)&dT,    g_dT);
    cudaGetSymbolAddress((void**)&xcT,   g_xcT);
    cudaGetSymbolAddress((void**)&zT,    g_zT);
    cudaGetSymbolAddress((void**)&bmT,   g_bmT);
    cudaGetSymbolAddress((void**)&cmT,   g_cmT);
    cudaGetSymbolAddress((void**)&ae,    g_aext);
    __nv_bfloat16 *wi, *wo, *wx, *wd;
    cudaGetSymbolAddress((void**)&wi, g_wi);
    cudaGetSymbolAddress((void**)&wo, g_wo);
    cudaGetSymbolAddress((void**)&wx, g_wx);
    cudaGetSymbolAddress((void**)&wd, g_wd);

    cudaFuncSetAttribute(gemm_bf<0>, cudaFuncAttributeMaxDynamicSharedMemorySize, GSMEM);
    cudaFuncSetAttribute(gemm_bf<1>, cudaFuncAttributeMaxDynamicSharedMemorySize, GSMEM);
    cudaFuncSetAttribute(gemm_bf<3>, cudaFuncAttributeMaxDynamicSharedMemorySize, GSMEM);

    embed_k<<<(ROWS * (DM / 4) + 255) / 256, 256>>>(seq, emb, resid);

    // ---- all weight-ext preps upfront ----
    for (int i = 0; i < NL; i++) {
        wprep_k<<<(2 * DI * DM + 255) / 256, 256>>>(
            in_proj_w + (size_t)i * 2 * DI * DM, wi + (size_t)i * (2 * DI) * KE_IN,
            2 * DI, 2 * DI, DM, DM);
        wprep_k<<<(DM * DI + 255) / 256, 256>>>(
            out_w + (size_t)i * DM * DI, wo + (size_t)i * DM * KE_BIG,
            DM, DM, DI, DI);
        wprep_k<<<(128 * DI + 255) / 256, 256>>>(
            x_proj_w + (size_t)i * XPN * DI, wx + (size_t)i * 128 * KE_BIG,
            XPN, 128, DI, DI);
        wprep_k<<<(DI * 64 + 255) / 256, 256>>>(
            dt_w + (size_t)i * DI * DTR, wd + (size_t)i * DI * KE_DT,
            DI, DI, DTR, 64);
    }

    for (int i = 0; i < NL; i++) {
        rmsnorm_k<<<ROWS, 256>>>(resid, norm_w + i * DM, ae);
        // in_proj: xz = hn @ W^T   (N=3072, Kext=2304, 72 iters)
        gemm_bf<0><<<dim3(24, 16, 1), 256, GSMEM>>>(
            ae, wi + (size_t)i * (2 * DI) * KE_IN, xz, nullptr,
            KE_IN, KE_IN / 32, 2 * DI, 2 * DI);

        conv_silu_k<<<(ROWS * DI) / 256, 256>>>(
            xz, conv_w + i * DI * 4, conv_b + i * DI, xcT, zT, ae);

        // x_proj: xdbl = xc @ W^T  (N=80 pad 128, Kext=4608, split-K z=16)
        cudaMemsetAsync(xdbl, 0, (size_t)ROWS * XPN * sizeof(float));
        gemm_bf<3><<<dim3(1, 16, 16), 256, GSMEM>>>(
            ae, wx + (size_t)i * 128 * KE_BIG, xdbl, nullptr,
            KE_BIG, KE_BIG / (16 * 32), XPN, XPN);

        // dt: dT = softplus(xdbl[:, :48] @ dt_w^T + dt_b), stored [c][l]
        dtprep_k<<<(ROWS * 64 + 255) / 256, 256>>>(xdbl, ae);
        transp_bc_k<<<(ROWS * 2 * DS + 255) / 256, 256>>>(xdbl, bmT, cmT);
        gemm_bf<1><<<dim3(12, 16, 1), 256, GSMEM>>>(
            ae, wd + (size_t)i * DI * KE_DT, dT, dt_b + i * DI,
            KE_DT, KE_DT / 32, DI, DI);

        // selective scan -> y ext (Kext=4608)
        scan_k<<<(BSZ * DI / 2 * 32) / 256, 256>>>(
            dT, xcT, zT, bmT, cmT, A_log + i * DI * DS, D_skip + i * DI, ae);

        // out_proj: resid += y @ W^T  (N=768, Kext=4608, split-K z=3, atomics)
        gemm_bf<3><<<dim3(6, 16, 3), 256, GSMEM>>>(
            ae, wo + (size_t)i * DM * KE_BIG, resid, nullptr,
            KE_BIG, KE_BIG / (3 * 32), DM, DM);
    }

    final_k<<<BSZ, 256>>>(resid, normf_w, mask, (float*)d_out);
}

// round 7
// speedup vs baseline: 2.5628x; 2.5628x over previous
#include <cuda_runtime.h>
#include <cuda_bf16.h>
#include <math.h>
#include <stdint.h>

#define BSZ 2
#define LSZ 1024
#define DM 768
#define NL 4
#define DI 1536
#define DS 16
#define DTR 48
#define XPN 80          // DTR + 2*DS
#define ROWS (BSZ*LSZ)  // 2048

// extended-K sizes (3 segments for bf16-split exact GEMM)
#define KE_IN   (3*DM)     // 2304
#define KE_BIG  (3*DI)     // 4608
#define KE_DT   (3*64)     // 192

#define STAGES 4
#define GSMEM (STAGES*16384)   // 64KB dynamic smem

#define TILE 32            // scan steps per staged tile

// ---------------- scratch (device globals; no allocation allowed) ----------
__device__ float g_resid[ROWS * DM];
__device__ float g_xz[ROWS * 2 * DI];
__device__ float g_xc[ROWS * DI];
__device__ float g_xdbl[ROWS * XPN];
__device__ float g_delta[ROWS * DI];
__device__ __nv_bfloat16 g_aext[ROWS * KE_BIG];          // activation ext (reused)
__device__ __nv_bfloat16 g_wi[NL][(2 * DI) * KE_IN];     // in_proj ext
__device__ __nv_bfloat16 g_wo[NL][DM * KE_BIG];          // out_proj ext
__device__ __nv_bfloat16 g_wx[NL][128 * KE_BIG];         // x_proj ext (N padded 128)
__device__ __nv_bfloat16 g_wd[NL][DI * KE_DT];           // dt ext

// ---------------- small helpers ----------------
__device__ __forceinline__ uint32_t smem_to_u32(const void* p) {
    uint32_t a;
    asm("{ .reg .u64 t; cvta.to.shared.u64 t, %1; cvt.u32.u64 %0, t; }"
        : "=r"(a) : "l"(p));
    return a;
}
__device__ __forceinline__ void cp16(uint32_t dst, const void* src) {
    asm volatile("cp.async.cg.shared.global [%0], [%1], 16;" :: "r"(dst), "l"(src));
}
__device__ __forceinline__ void cp8(uint32_t dst, const void* src) {
    asm volatile("cp.async.ca.shared.global [%0], [%1], 8;" :: "r"(dst), "l"(src));
}
__device__ __forceinline__ void ldsm4(uint32_t* r, uint32_t addr) {
    asm volatile("ldmatrix.sync.aligned.m8n8.x4.shared.b16 {%0,%1,%2,%3}, [%4];"
        : "=r"(r[0]), "=r"(r[1]), "=r"(r[2]), "=r"(r[3]) : "r"(addr));
}
__device__ __forceinline__ void mma16816(float* c, const uint32_t* a, const uint32_t* b) {
    asm volatile("mma.sync.aligned.m16n8k16.row.col.f32.bf16.bf16.f32 "
        "{%0,%1,%2,%3}, {%4,%5,%6,%7}, {%8,%9}, {%0,%1,%2,%3};"
        : "+f"(c[0]), "+f"(c[1]), "+f"(c[2]), "+f"(c[3])
        : "r"(a[0]), "r"(a[1]), "r"(a[2]), "r"(a[3]), "r"(b[0]), "r"(b[1]));
}
__device__ __forceinline__ void bsplit(float v, __nv_bfloat16& h, __nv_bfloat16& l) {
    h = __float2bfloat16(v);
    l = __float2bfloat16(v - __bfloat162float(h));
}
__device__ __forceinline__ float softplus_f(float v) {
    return fmaxf(v, 0.f) + __logf(1.f + __expf(-fabsf(v)));
}

__device__ __forceinline__ float block_sum(float v) {
    __shared__ float sh[8];
    __syncthreads();
#pragma unroll
    for (int o = 16; o; o >>= 1) v += __shfl_xor_sync(0xffffffffu, v, o);
    if ((threadIdx.x & 31) == 0) sh[threadIdx.x >> 5] = v;
    __syncthreads();
    if (threadIdx.x < 32) {
        float t = (threadIdx.x < (blockDim.x >> 5)) ? sh[threadIdx.x] : 0.f;
#pragma unroll
        for (int o = 4; o; o >>= 1) t += __shfl_xor_sync(0xffffffffu, t, o);
        if (threadIdx.x == 0) sh[0] = t;
    }
    __syncthreads();
    return sh[0];
}

// ---------------- embedding gather ----------------
__global__ void embed_k(const int* __restrict__ seq, const float* __restrict__ emb,
                        float* __restrict__ resid) {
    int i = blockIdx.x * blockDim.x + threadIdx.x;
    if (i >= ROWS * (DM / 4)) return;
    int row = i / (DM / 4), c4 = i % (DM / 4);
    int tok = seq[row];
    reinterpret_cast<float4*>(resid)[(size_t)row * (DM / 4) + c4] =
        reinterpret_cast<const float4*>(emb)[(size_t)tok * (DM / 4) + c4];
}

// ---------------- rmsnorm: writes ext layout (Kext=2304) -------------------
__global__ void rmsnorm_k(const float* __restrict__ x, const float* __restrict__ w,
                          __nv_bfloat16* __restrict__ ae) {
    int row = blockIdx.x;
    const float* xr = x + (size_t)row * DM;
    float s = 0.f;
    for (int c = threadIdx.x; c < DM; c += blockDim.x) { float v = xr[c]; s += v * v; }
    s = block_sum(s);
    float inv = rsqrtf(s / (float)DM + 1e-5f);
    __nv_bfloat16* ar = ae + (size_t)row * KE_IN;
    for (int c = threadIdx.x; c < DM; c += blockDim.x) {
        float v = xr[c] * inv * w[c];
        __nv_bfloat16 h, l; bsplit(v, h, l);
        ar[c] = h; ar[c + DM] = h; ar[c + 2 * DM] = l;
    }
}

// ---------------- weight prep: fp32 [N,Ksrc] -> ext bf16 [Npad, 3*Kpad] ----
__global__ void wprep_k(const float* __restrict__ w, __nv_bfloat16* __restrict__ e,
                        int N, int Npad, int Ksrc, int Kpad) {
    int i = blockIdx.x * blockDim.x + threadIdx.x;
    if (i >= Npad * Kpad) return;
    int n = i / Kpad, k = i - n * Kpad;
    float v = (n < N && k < Ksrc) ? w[(size_t)n * Ksrc + k] : 0.f;
    __nv_bfloat16 h, l; bsplit(v, h, l);
    __nv_bfloat16* er = e + (size_t)n * (3 * Kpad);
    er[k] = h; er[k + Kpad] = l; er[k + 2 * Kpad] = h;
}

// ---------------- dt A prep: xdbl[:, :48] -> ext [ROWS, 192] ---------------
__global__ void dtprep_k(const float* __restrict__ xdbl, __nv_bfloat16* __restrict__ ae) {
    int i = blockIdx.x * blockDim.x + threadIdx.x;
    if (i >= ROWS * 64) return;
    int r = i >> 6, k = i & 63;
    float v = (k < DTR) ? xdbl[(size_t)r * XPN + k] : 0.f;
    __nv_bfloat16 h, l; bsplit(v, h, l);
    __nv_bfloat16* ar = ae + (size_t)r * KE_DT;
    ar[k] = h; ar[k + 64] = h; ar[k + 128] = l;
}

// ---------------- depthwise conv + silu: fp32 + ext (Kext=4608) ------------
__global__ void conv_silu_k(const float* __restrict__ xz, const float* __restrict__ cw,
                            const float* __restrict__ cb, float* __restrict__ xc,
                            __nv_bfloat16* __restrict__ ae) {
    int i = blockIdx.x * blockDim.x + threadIdx.x;
    if (i >= ROWS * DI) return;
    int d = i % DI;
    int row = i / DI;
    int l = row & (LSZ - 1);
    float acc = cb[d];
#pragma unroll
    for (int k = 0; k < 4; k++) {
        int l2 = l + k - 3;
        if (l2 >= 0)
            acc += xz[(size_t)(row + k - 3) * (2 * DI) + d] * cw[d * 4 + k];
    }
    acc = acc / (1.f + __expf(-acc));
    xc[i] = acc;
    __nv_bfloat16 h, lo; bsplit(acc, h, lo);
    __nv_bfloat16* ar = ae + (size_t)row * KE_BIG;
    ar[d] = h; ar[d + DI] = h; ar[d + 2 * DI] = lo;
}

// ---------------- bf16 tensor-core GEMM: C = Aext @ Wext^T -----------------
// CTA tile 128x128x32, 8 warps (4x2), 4-stage cp.async pipeline.
// EPI: 0 = store, 1 = softplus(acc + bias[n]), 3 = atomicAdd (guard n < N)
template <int EPI>
__global__ void __launch_bounds__(256) gemm_bf(
    const __nv_bfloat16* __restrict__ Aext, const __nv_bfloat16* __restrict__ Wext,
    float* __restrict__ C, const float* __restrict__ bias,
    int Kext, int kIters, int N, int ldc) {
    extern __shared__ __align__(16) uint8_t smem[];
    int tid = threadIdx.x;
    int wid = tid >> 5, lane = tid & 31;
    int m0 = blockIdx.y * 128, n0 = blockIdx.x * 128;
    int kbase = blockIdx.z * kIters * 32;

    int warp_m = wid & 3, warp_n = wid >> 2;   // 4 x 2 warp grid

    int lrow = tid >> 2;       // 0..63
    int lch = tid & 3;         // 0..3
    const char* Ag = (const char*)(Aext + (size_t)(m0 + lrow) * Kext + kbase + lch * 8);
    const char* Bg = (const char*)(Wext + (size_t)(n0 + lrow) * Kext + kbase + lch * 8);
    size_t rstep = (size_t)64 * Kext * 2;
    uint32_t su = smem_to_u32(smem);
    uint32_t dst0 = (uint32_t)(lrow * 64 + ((lch ^ ((lrow >> 1) & 3)) * 16));

    float acc[2][8][4];
#pragma unroll
    for (int a = 0; a < 2; a++)
#pragma unroll
        for (int b = 0; b < 8; b++)
#pragma unroll
            for (int c = 0; c < 4; c++) acc[a][b][c] = 0.f;

#define LOAD_STAGE(st, kt) do { \
    if ((kt) < kIters) { \
        uint32_t _o = (uint32_t)(st) * 16384 + dst0; \
        size_t _g = (size_t)(kt) * 64; \
        cp16(su + _o, Ag + _g); \
        cp16(su + _o + 4096, Ag + rstep + _g); \
        cp16(su + _o + 8192, Bg + _g); \
        cp16(su + _o + 12288, Bg + rstep + _g); \
    } \
    asm volatile("cp.async.commit_group;"); \
} while (0)

#pragma unroll
    for (int s = 0; s < STAGES - 1; s++) LOAD_STAGE(s, s);

    for (int kt = 0; kt < kIters; kt++) {
        asm volatile("cp.async.wait_group %0;" :: "n"(STAGES - 2) : "memory");
        __syncthreads();
        LOAD_STAGE((kt + STAGES - 1) & (STAGES - 1), kt + STAGES - 1);
        int st = kt & (STAGES - 1);
        uint32_t baseA = su + st * 16384;
        uint32_t baseB = baseA + 8192;
#pragma unroll
        for (int ks = 0; ks < 2; ks++) {
            int lr16 = lane & 15;
            int ach = ks * 2 + (lane >> 4);
            uint32_t afr[2][4];
#pragma unroll
            for (int mf = 0; mf < 2; mf++) {
                int r = warp_m * 32 + mf * 16 + lr16;
                ldsm4(afr[mf], baseA + r * 64 + ((ach ^ ((r >> 1) & 3)) * 16));
            }
#pragma unroll
            for (int np = 0; np < 4; np++) {
                int r = warp_n * 64 + np * 16 + lr16;
                uint32_t bfr[4];
                ldsm4(bfr, baseB + r * 64 + ((ach ^ ((r >> 1) & 3)) * 16));
                uint32_t b0[2] = {bfr[0], bfr[2]};
                uint32_t b1[2] = {bfr[1], bfr[3]};
#pragma unroll
                for (int mf = 0; mf < 2; mf++) {
                    mma16816(acc[mf][np * 2], afr[mf], b0);
                    mma16816(acc[mf][np * 2 + 1], afr[mf], b1);
                }
            }
        }
    }

    int trow = lane >> 2, tc2 = (lane & 3) * 2;
#pragma unroll
    for (int mf = 0; mf < 2; mf++) {
#pragma unroll
        for (int nf = 0; nf < 8; nf++) {
            int n = n0 + warp_n * 64 + nf * 8 + tc2;
            int m = m0 + warp_m * 32 + mf * 16 + trow;
#pragma unroll
            for (int hh = 0; hh < 2; hh++) {
                float v0 = acc[mf][nf][hh * 2];
                float v1 = acc[mf][nf][hh * 2 + 1];
                int mr = m + hh * 8;
                if (EPI == 1) {
                    v0 = softplus_f(v0 + bias[n]);
                    v1 = softplus_f(v1 + bias[n + 1]);
                }
                if (EPI == 3) {
                    if (n < N)     atomicAdd(&C[(size_t)mr * ldc + n], v0);
                    if (n + 1 < N) atomicAdd(&C[(size_t)mr * ldc + n + 1], v1);
                } else {
                    *reinterpret_cast<float2*>(&C[(size_t)mr * ldc + n]) =
                        make_float2(v0, v1);
                }
            }
        }
    }
#undef LOAD_STAGE
}

// ---------------- selective scan: block-staged smem tiles ------------------
// One CTA = 16 consecutive channels (8 warps, 2 ch/warp, 16 states each).
// Operand tiles [TILE steps][16] staged via cp.async from ROW-MAJOR buffers.
__global__ void __launch_bounds__(256) scan_k(
    const float* __restrict__ delta, const float* __restrict__ xc,
    const float* __restrict__ xz, const float* __restrict__ xdbl,
    const float* __restrict__ A_log, const float* __restrict__ dski,
    __nv_bfloat16* __restrict__ ye) {
    // streams: 0=delta 1=u 2=z 3=B 4=C ; [stream][buf][TILE*16]
    __shared__ __align__(16) float stage[5][2][TILE * 16];
    int tid = threadIdx.x;
    int wid = tid >> 5, lane = tid & 31;
    int half = lane >> 4, s = lane & 15;
    int c0 = blockIdx.x * 16;
    int b = c0 / DI, d0 = c0 % DI;
    int cib = wid * 2 + half;          // channel-in-block 0..15
    int d = d0 + cib;

    float As = -__expf(A_log[d * DS + s]);
    float dsk = dski[d];

    // loader mapping: row = tid>>3 (0..31), 8-byte piece = (tid&7)*8
    int lrow = tid >> 3;
    int lcol = (tid & 7) * 8;   // byte offset within 64B row
    const char* dbase = (const char*)(delta + (size_t)b * LSZ * DI + d0) + lcol;
    const char* ubase = (const char*)(xc + (size_t)b * LSZ * DI + d0) + lcol;
    const char* zbase = (const char*)(xz + (size_t)b * LSZ * (2 * DI) + DI + d0) + lcol;
    const char* bbase = (const char*)(xdbl + (size_t)b * LSZ * XPN + DTR) + lcol;
    const char* cbase = bbase + DS * 4;
    uint32_t su = smem_to_u32(stage);
    uint32_t soff = (uint32_t)(lrow * 64 + lcol);
#define SADDR(stream, buf) (su + ((stream) * 2 + (buf)) * (TILE * 64))

#define SCAN_LOAD(buf, t) do { \
    if ((t) < LSZ / TILE) { \
        size_t gl = (size_t)((t) * TILE + lrow); \
        cp8(SADDR(0, buf) + soff, dbase + gl * (DI * 4)); \
        cp8(SADDR(1, buf) + soff, ubase + gl * (DI * 4)); \
        cp8(SADDR(2, buf) + soff, zbase + gl * (2 * DI * 4)); \
        cp8(SADDR(3, buf) + soff, bbase + gl * (XPN * 4)); \
        cp8(SADDR(4, buf) + soff, cbase + gl * (XPN * 4)); \
    } \
    asm volatile("cp.async.commit_group;"); \
} while (0)

    SCAN_LOAD(0, 0);
    SCAN_LOAD(1, 1);

    float h = 0.f;
    float praw = 0.f, ppart = 0.f;    // raw p (step l-1), partial p (step l-2)
    float u1 = 0.f, z1 = 0.f, u2 = 0.f, z2 = 0.f;
    __nv_bfloat16* yr = ye + (size_t)b * LSZ * KE_BIG + d;

    const int NT = LSZ / TILE;
    for (int t = 0; t < NT; t++) {
        asm volatile("cp.async.wait_group 1;" ::: "memory");
        __syncthreads();
        int buf = t & 1;
        const float* sd = stage[0][buf];
        const float* suu = stage[1][buf];
        const float* sz = stage[2][buf];
        const float* sb = stage[3][buf];
        const float* sc = stage[4][buf];
#pragma unroll
        for (int j = 0; j < TILE; j++) {
            int l = t * TILE + j;
            float dl = sd[j * 16 + cib];
            float u  = suu[j * 16 + cib];
            float z  = sz[j * 16 + cib];
            float bm = sb[j * 16 + s];
            float cm = sc[j * 16 + s];
            float a8 = __shfl_xor_sync(0xffffffffu, praw, 8);
            float b2 = __shfl_xor_sync(0xffffffffu, ppart, 2);
            float dA = __expf(dl * As);
            float dlu = dl * u;
            praw += a8;
            ppart += b2;
            float a4 = __shfl_xor_sync(0xffffffffu, praw, 4);
            float b1 = __shfl_xor_sync(0xffffffffu, ppart, 1);
            h = dA * h + dlu * bm;
            float pnew = h * cm;
            praw += a4;
            ppart += b1;
            if (l >= 2 && s == 0) {
                float yv = (ppart + u2 * dsk) * (z2 / (1.f + __expf(-z2)));
                __nv_bfloat16 hh, ll; bsplit(yv, hh, ll);
                __nv_bfloat16* yp = yr + (size_t)(l - 2) * KE_BIG;
                yp[0] = hh; yp[DI] = hh; yp[2 * DI] = ll;
            }
            ppart = praw; praw = pnew;
            u2 = u1; z2 = z1; u1 = u; z1 = z;
        }
        __syncthreads();
        SCAN_LOAD(buf, t + 2);
    }
    // drain last two steps
    ppart += __shfl_xor_sync(0xffffffffu, ppart, 2);
    ppart += __shfl_xor_sync(0xffffffffu, ppart, 1);
    praw += __shfl_xor_sync(0xffffffffu, praw, 8);
    praw += __shfl_xor_sync(0xffffffffu, praw, 4);
    praw += __shfl_xor_sync(0xffffffffu, praw, 2);
    praw += __shfl_xor_sync(0xffffffffu, praw, 1);
    if (s == 0) {
        float yv = (ppart + u2 * dsk) * (z2 / (1.f + __expf(-z2)));
        __nv_bfloat16 hh, ll; bsplit(yv, hh, ll);
        __nv_bfloat16* yp = yr + (size_t)(LSZ - 2) * KE_BIG;
        yp[0] = hh; yp[DI] = hh; yp[2 * DI] = ll;
        yv = (praw + u1 * dsk) * (z1 / (1.f + __expf(-z1)));
        bsplit(yv, hh, ll);
        yp = yr + (size_t)(LSZ - 1) * KE_BIG;
        yp[0] = hh; yp[DI] = hh; yp[2 * DI] = ll;
    }
#undef SCAN_LOAD
#undef SADDR
}

// ---------------- final: last-token rmsnorm ----------------
__global__ void final_k(const float* __restrict__ resid, const float* __restrict__ nw,
                        const int* __restrict__ mask, float* __restrict__ out) {
    int b = blockIdx.x;
    float ms = 0.f;
    for (int i = threadIdx.x; i < LSZ; i += blockDim.x) ms += (float)mask[b * LSZ + i];
    ms = block_sum(ms);
    int last = (int)(ms + 0.5f) - 1;
    const float* xr = resid + ((size_t)b * LSZ + last) * DM;
    float sacc = 0.f;
    for (int cidx = threadIdx.x; cidx < DM; cidx += blockDim.x) {
        float v = xr[cidx];
        sacc += v * v;
    }
    sacc = block_sum(sacc);
    float inv = rsqrtf(sacc / (float)DM + 1e-5f);
    for (int cidx = threadIdx.x; cidx < DM; cidx += blockDim.x)
        out[b * DM + cidx] = xr[cidx] * inv * nw[cidx];
}

// ---------------- driver ----------------
extern "C" void kernel_launch(void* const* d_in, const int* in_sizes, int n_in,
                              void* d_out, int out_size) {
    const int*   seq       = (const int*)d_in[0];
    const int*   mask      = (const int*)d_in[1];
    const float* emb       = (const float*)d_in[2];
    const float* norm_w    = (const float*)d_in[3];
    const float* in_proj_w = (const float*)d_in[4];
    const float* conv_w    = (const float*)d_in[5];
    const float* conv_b    = (const float*)d_in[6];
    const float* x_proj_w  = (const float*)d_in[7];
    const float* dt_w      = (const float*)d_in[8];
    const float* dt_b      = (const float*)d_in[9];
    const float* A_log     = (const float*)d_in[10];
    const float* D_skip    = (const float*)d_in[11];
    const float* out_w     = (const float*)d_in[12];
    const float* normf_w   = (const float*)d_in[13];

    float *resid, *xz, *xc, *xdbl, *delta;
    __nv_bfloat16 *ae;
    cudaGetSymbolAddress((void**)&resid, g_resid);
    cudaGetSymbolAddress((void**)&xz,    g_xz);
    cudaGetSymbolAddress((void**)&xc,    g_xc);
    cudaGetSymbolAddress((void**)&xdbl,  g_xdbl);
    cudaGetSymbolAddress((void**)&delta, g_delta);
    cudaGetSymbolAddress((void**)&ae,    g_aext);
    __nv_bfloat16 *wi, *wo, *wx, *wd;
    cudaGetSymbolAddress((void**)&wi, g_wi);
    cudaGetSymbolAddress((void**)&wo, g_wo);
    cudaGetSymbolAddress((void**)&wx, g_wx);
    cudaGetSymbolAddress((void**)&wd, g_wd);

    cudaFuncSetAttribute(gemm_bf<0>, cudaFuncAttributeMaxDynamicSharedMemorySize, GSMEM);
    cudaFuncSetAttribute(gemm_bf<1>, cudaFuncAttributeMaxDynamicSharedMemorySize, GSMEM);
    cudaFuncSetAttribute(gemm_bf<3>, cudaFuncAttributeMaxDynamicSharedMemorySize, GSMEM);

    embed_k<<<(ROWS * (DM / 4) + 255) / 256, 256>>>(seq, emb, resid);

    // ---- all weight-ext preps upfront ----
    for (int i = 0; i < NL; i++) {
        wprep_k<<<(2 * DI * DM + 255) / 256, 256>>>(
            in_proj_w + (size_t)i * 2 * DI * DM, wi + (size_t)i * (2 * DI) * KE_IN,
            2 * DI, 2 * DI, DM, DM);
        wprep_k<<<(DM * DI + 255) / 256, 256>>>(
            out_w + (size_t)i * DM * DI, wo + (size_t)i * DM * KE_BIG,
            DM, DM, DI, DI);
        wprep_k<<<(128 * DI + 255) / 256, 256>>>(
            x_proj_w + (size_t)i * XPN * DI, wx + (size_t)i * 128 * KE_BIG,
            XPN, 128, DI, DI);
        wprep_k<<<(DI * 64 + 255) / 256, 256>>>(
            dt_w + (size_t)i * DI * DTR, wd + (size_t)i * DI * KE_DT,
            DI, DI, DTR, 64);
    }

    for (int i = 0; i < NL; i++) {
        rmsnorm_k<<<ROWS, 256>>>(resid, norm_w + i * DM, ae);
        // in_proj: xz = hn @ W^T   (N=3072, Kext=2304, 72 iters)
        gemm_bf<0><<<dim3(24, 16, 1), 256, GSMEM>>>(
            ae, wi + (size_t)i * (2 * DI) * KE_IN, xz, nullptr,
            KE_IN, KE_IN / 32, 2 * DI, 2 * DI);

        conv_silu_k<<<(ROWS * DI) / 256, 256>>>(
            xz, conv_w + i * DI * 4, conv_b + i * DI, xc, ae);

        // x_proj: xdbl = xc @ W^T  (N=80 pad 128, Kext=4608, split-K z=16)
        cudaMemsetAsync(xdbl, 0, (size_t)ROWS * XPN * sizeof(float));
        gemm_bf<3><<<dim3(1, 16, 16), 256, GSMEM>>>(
            ae, wx + (size_t)i * 128 * KE_BIG, xdbl, nullptr,
            KE_BIG, KE_BIG / (16 * 32), XPN, XPN);

        // dt: delta = softplus(xdbl[:, :48] @ dt_w^T + dt_b)
        dtprep_k<<<(ROWS * 64 + 255) / 256, 256>>>(xdbl, ae);
        gemm_bf<1><<<dim3(12, 16, 1), 256, GSMEM>>>(
            ae, wd + (size_t)i * DI * KE_DT, delta, dt_b + i * DI,
            KE_DT, KE_DT / 32, DI, DI);

        // selective scan -> y ext (Kext=4608)
        scan_k<<<BSZ * DI / 16, 256>>>(
            delta, xc, xz, xdbl, A_log + i * DI * DS, D_skip + i * DI, ae);

        // out_proj: resid += y @ W^T  (N=768, Kext=4608, split-K z=3, atomics)
        gemm_bf<3><<<dim3(6, 16, 3), 256, GSMEM>>>(
            ae, wo + (size_t)i * DM * KE_BIG, resid, nullptr,
            KE_BIG, KE_BIG / (3 * 32), DM, DM);
    }

    final_k<<<BSZ, 256>>>(resid, normf_w, mask, (float*)d_out);
}

// round 8
// speedup vs baseline: 2.7522x; 1.0739x over previous
#include <cuda_runtime.h>
#include <cuda_bf16.h>
#include <math.h>
#include <stdint.h>

#define BSZ 2
#define LSZ 1024
#define DM 768
#define NL 4
#define DI 1536
#define DS 16
#define DTR 48
#define XPN 80          // DTR + 2*DS
#define ROWS (BSZ*LSZ)  // 2048

// extended-K sizes (3 segments for bf16-split exact GEMM)
#define KE_IN   (3*DM)     // 2304
#define KE_BIG  (3*DI)     // 4608
#define KE_DT   (3*64)     // 192

#define STAGES 3
#define GSMEM (STAGES*16384)   // 48KB dynamic smem -> 2 CTAs/SM

#define TILE 32            // scan steps per staged tile
#define SCH 24             // scan channels per CTA (128 CTAs total)

// ---------------- scratch (device globals; no allocation allowed) ----------
__device__ float g_resid[ROWS * DM];
__device__ float g_xz[ROWS * 2 * DI];
__device__ float g_xc[ROWS * DI];
__device__ float g_xdbl[ROWS * XPN];
__device__ float g_delta[ROWS * DI];
__device__ __nv_bfloat16 g_aext[ROWS * KE_BIG];          // activation ext (reused)
__device__ __nv_bfloat16 g_wi[NL][(2 * DI) * KE_IN];     // in_proj ext
__device__ __nv_bfloat16 g_wo[NL][DM * KE_BIG];          // out_proj ext
__device__ __nv_bfloat16 g_wx[NL][128 * KE_BIG];         // x_proj ext (N padded 128)
__device__ __nv_bfloat16 g_wd[NL][DI * KE_DT];           // dt ext

// ---------------- small helpers ----------------
__device__ __forceinline__ uint32_t smem_to_u32(const void* p) {
    uint32_t a;
    asm("{ .reg .u64 t; cvta.to.shared.u64 t, %1; cvt.u32.u64 %0, t; }"
        : "=r"(a) : "l"(p));
    return a;
}
__device__ __forceinline__ void cp16(uint32_t dst, const void* src) {
    asm volatile("cp.async.cg.shared.global [%0], [%1], 16;" :: "r"(dst), "l"(src));
}
__device__ __forceinline__ void cp8(uint32_t dst, const void* src) {
    asm volatile("cp.async.ca.shared.global [%0], [%1], 8;" :: "r"(dst), "l"(src));
}
__device__ __forceinline__ void ldsm4(uint32_t* r, uint32_t addr) {
    asm volatile("ldmatrix.sync.aligned.m8n8.x4.shared.b16 {%0,%1,%2,%3}, [%4];"
        : "=r"(r[0]), "=r"(r[1]), "=r"(r[2]), "=r"(r[3]) : "r"(addr));
}
__device__ __forceinline__ void mma16816(float* c, const uint32_t* a, const uint32_t* b) {
    asm volatile("mma.sync.aligned.m16n8k16.row.col.f32.bf16.bf16.f32 "
        "{%0,%1,%2,%3}, {%4,%5,%6,%7}, {%8,%9}, {%0,%1,%2,%3};"
        : "+f"(c[0]), "+f"(c[1]), "+f"(c[2]), "+f"(c[3])
        : "r"(a[0]), "r"(a[1]), "r"(a[2]), "r"(a[3]), "r"(b[0]), "r"(b[1]));
}
__device__ __forceinline__ void bsplit(float v, __nv_bfloat16& h, __nv_bfloat16& l) {
    h = __float2bfloat16(v);
    l = __float2bfloat16(v - __bfloat162float(h));
}
__device__ __forceinline__ float softplus_f(float v) {
    return fmaxf(v, 0.f) + __logf(1.f + __expf(-fabsf(v)));
}

__device__ __forceinline__ float block_sum(float v) {
    __shared__ float sh[8];
    __syncthreads();
#pragma unroll
    for (int o = 16; o; o >>= 1) v += __shfl_xor_sync(0xffffffffu, v, o);
    if ((threadIdx.x & 31) == 0) sh[threadIdx.x >> 5] = v;
    __syncthreads();
    if (threadIdx.x < 32) {
        float t = (threadIdx.x < (blockDim.x >> 5)) ? sh[threadIdx.x] : 0.f;
#pragma unroll
        for (int o = 4; o; o >>= 1) t += __shfl_xor_sync(0xffffffffu, t, o);
        if (threadIdx.x == 0) sh[0] = t;
    }
    __syncthreads();
    return sh[0];
}

// ---------------- embedding gather ----------------
__global__ void embed_k(const int* __restrict__ seq, const float* __restrict__ emb,
                        float* __restrict__ resid) {
    int i = blockIdx.x * blockDim.x + threadIdx.x;
    if (i >= ROWS * (DM / 4)) return;
    int row = i / (DM / 4), c4 = i % (DM / 4);
    int tok = seq[row];
    reinterpret_cast<float4*>(resid)[(size_t)row * (DM / 4) + c4] =
        reinterpret_cast<const float4*>(emb)[(size_t)tok * (DM / 4) + c4];
}

// ---------------- rmsnorm: writes ext layout (Kext=2304) -------------------
__global__ void rmsnorm_k(const float* __restrict__ x, const float* __restrict__ w,
                          __nv_bfloat16* __restrict__ ae) {
    int row = blockIdx.x;
    const float* xr = x + (size_t)row * DM;
    float s = 0.f;
    for (int c = threadIdx.x; c < DM; c += blockDim.x) { float v = xr[c]; s += v * v; }
    s = block_sum(s);
    float inv = rsqrtf(s / (float)DM + 1e-5f);
    __nv_bfloat16* ar = ae + (size_t)row * KE_IN;
    for (int c4 = threadIdx.x * 4; c4 < DM; c4 += blockDim.x * 4) {
        float4 xv = *reinterpret_cast<const float4*>(xr + c4);
        float4 wv = *reinterpret_cast<const float4*>(w + c4);
        union { __nv_bfloat16 b[4]; uint2 u; } hq, lq;
        float vv[4] = {xv.x * wv.x, xv.y * wv.y, xv.z * wv.z, xv.w * wv.w};
#pragma unroll
        for (int j = 0; j < 4; j++) bsplit(vv[j] * inv, hq.b[j], lq.b[j]);
        *reinterpret_cast<uint2*>(ar + c4) = hq.u;
        *reinterpret_cast<uint2*>(ar + DM + c4) = hq.u;
        *reinterpret_cast<uint2*>(ar + 2 * DM + c4) = lq.u;
    }
}

// ---------------- weight prep (vectorized x4) ------------------------------
__global__ void wprep_k(const float* __restrict__ w, __nv_bfloat16* __restrict__ e,
                        int N, int Npad, int Ksrc, int Kpad) {
    int i4 = (blockIdx.x * blockDim.x + threadIdx.x) * 4;
    if (i4 >= Npad * Kpad) return;
    int n = i4 / Kpad, k = i4 - n * Kpad;
    float4 v = make_float4(0.f, 0.f, 0.f, 0.f);
    if (n < N && k < Ksrc)
        v = *reinterpret_cast<const float4*>(w + (size_t)n * Ksrc + k);
    union { __nv_bfloat16 b[4]; uint2 u; } hq, lq;
    bsplit(v.x, hq.b[0], lq.b[0]); bsplit(v.y, hq.b[1], lq.b[1]);
    bsplit(v.z, hq.b[2], lq.b[2]); bsplit(v.w, hq.b[3], lq.b[3]);
    __nv_bfloat16* er = e + (size_t)n * (3 * Kpad);
    *reinterpret_cast<uint2*>(er + k) = hq.u;
    *reinterpret_cast<uint2*>(er + Kpad + k) = lq.u;
    *reinterpret_cast<uint2*>(er + 2 * Kpad + k) = hq.u;
}

// ---------------- dt A prep: xdbl[:, :48] -> ext [ROWS, 192] (x4) ----------
__global__ void dtprep_k(const float* __restrict__ xdbl, __nv_bfloat16* __restrict__ ae) {
    int i4 = (blockIdx.x * blockDim.x + threadIdx.x) * 4;
    if (i4 >= ROWS * 64) return;
    int r = i4 >> 6, k = i4 & 63;
    float4 v = make_float4(0.f, 0.f, 0.f, 0.f);
    if (k < DTR)
        v = *reinterpret_cast<const float4*>(xdbl + (size_t)r * XPN + k);
    union { __nv_bfloat16 b[4]; uint2 u; } hq, lq;
    bsplit(v.x, hq.b[0], lq.b[0]); bsplit(v.y, hq.b[1], lq.b[1]);
    bsplit(v.z, hq.b[2], lq.b[2]); bsplit(v.w, hq.b[3], lq.b[3]);
    __nv_bfloat16* ar = ae + (size_t)r * KE_DT;
    *reinterpret_cast<uint2*>(ar + k) = hq.u;
    *reinterpret_cast<uint2*>(ar + 64 + k) = hq.u;
    *reinterpret_cast<uint2*>(ar + 128 + k) = lq.u;
}

// ---------------- depthwise conv + silu: fp32 + ext (Kext=4608) ------------
__global__ void conv_silu_k(const float* __restrict__ xz, const float* __restrict__ cw,
                            const float* __restrict__ cb, float* __restrict__ xc,
                            __nv_bfloat16* __restrict__ ae) {
    int i = blockIdx.x * blockDim.x + threadIdx.x;
    if (i >= ROWS * DI) return;
    int d = i % DI;
    int row = i / DI;
    int l = row & (LSZ - 1);
    float acc = cb[d];
#pragma unroll
    for (int k = 0; k < 4; k++) {
        int l2 = l + k - 3;
        if (l2 >= 0)
            acc += xz[(size_t)(row + k - 3) * (2 * DI) + d] * cw[d * 4 + k];
    }
    acc = acc / (1.f + __expf(-acc));
    xc[i] = acc;
    __nv_bfloat16 h, lo; bsplit(acc, h, lo);
    __nv_bfloat16* ar = ae + (size_t)row * KE_BIG;
    ar[d] = h; ar[d + DI] = h; ar[d + 2 * DI] = lo;
}

// ---------------- bf16 tensor-core GEMM: C = Aext @ Wext^T -----------------
// CTA tile 128x128x32, 8 warps (4x2), 3-stage cp.async, 2 CTAs/SM.
// EPI: 0 = store, 1 = softplus(acc + bias[n]), 3 = atomicAdd (guard n < N)
template <int EPI>
__global__ void __launch_bounds__(256, 2) gemm_bf(
    const __nv_bfloat16* __restrict__ Aext, const __nv_bfloat16* __restrict__ Wext,
    float* __restrict__ C, const float* __restrict__ bias,
    int Kext, int kIters, int N, int ldc) {
    extern __shared__ __align__(16) uint8_t smem[];
    int tid = threadIdx.x;
    int wid = tid >> 5, lane = tid & 31;
    int m0 = blockIdx.y * 128, n0 = blockIdx.x * 128;
    int kbase = blockIdx.z * kIters * 32;

    int warp_m = wid & 3, warp_n = wid >> 2;   // 4 x 2 warp grid

    int lrow = tid >> 2;       // 0..63
    int lch = tid & 3;         // 0..3
    const char* Ag = (const char*)(Aext + (size_t)(m0 + lrow) * Kext + kbase + lch * 8);
    const char* Bg = (const char*)(Wext + (size_t)(n0 + lrow) * Kext + kbase + lch * 8);
    size_t rstep = (size_t)64 * Kext * 2;
    uint32_t su = smem_to_u32(smem);
    uint32_t dst0 = (uint32_t)(lrow * 64 + ((lch ^ ((lrow >> 1) & 3)) * 16));

    float acc[2][8][4];
#pragma unroll
    for (int a = 0; a < 2; a++)
#pragma unroll
        for (int b = 0; b < 8; b++)
#pragma unroll
            for (int c = 0; c < 4; c++) acc[a][b][c] = 0.f;

#define LOAD_STAGE(st, kt) do { \
    if ((kt) < kIters) { \
        uint32_t _o = (uint32_t)(st) * 16384 + dst0; \
        size_t _g = (size_t)(kt) * 64; \
        cp16(su + _o, Ag + _g); \
        cp16(su + _o + 4096, Ag + rstep + _g); \
        cp16(su + _o + 8192, Bg + _g); \
        cp16(su + _o + 12288, Bg + rstep + _g); \
    } \
    asm volatile("cp.async.commit_group;"); \
} while (0)

    LOAD_STAGE(0, 0);
    LOAD_STAGE(1, 1);

    int cur = 0;
    for (int kt = 0; kt < kIters; kt++) {
        asm volatile("cp.async.wait_group 1;" ::: "memory");
        __syncthreads();
        int nst = cur + 2; if (nst >= STAGES) nst -= STAGES;
        LOAD_STAGE(nst, kt + 2);
        uint32_t baseA = su + cur * 16384;
        uint32_t baseB = baseA + 8192;
#pragma unroll
        for (int ks = 0; ks < 2; ks++) {
            int lr16 = lane & 15;
            int ach = ks * 2 + (lane >> 4);
            uint32_t afr[2][4];
#pragma unroll
            for (int mf = 0; mf < 2; mf++) {
                int r = warp_m * 32 + mf * 16 + lr16;
                ldsm4(afr[mf], baseA + r * 64 + ((ach ^ ((r >> 1) & 3)) * 16));
            }
#pragma unroll
            for (int np = 0; np < 4; np++) {
                int r = warp_n * 64 + np * 16 + lr16;
                uint32_t bfr[4];
                ldsm4(bfr, baseB + r * 64 + ((ach ^ ((r >> 1) & 3)) * 16));
                uint32_t b0[2] = {bfr[0], bfr[2]};
                uint32_t b1[2] = {bfr[1], bfr[3]};
#pragma unroll
                for (int mf = 0; mf < 2; mf++) {
                    mma16816(acc[mf][np * 2], afr[mf], b0);
                    mma16816(acc[mf][np * 2 + 1], afr[mf], b1);
                }
            }
        }
        cur = cur + 1 == STAGES ? 0 : cur + 1;
    }

    int trow = lane >> 2, tc2 = (lane & 3) * 2;
#pragma unroll
    for (int mf = 0; mf < 2; mf++) {
#pragma unroll
        for (int nf = 0; nf < 8; nf++) {
            int n = n0 + warp_n * 64 + nf * 8 + tc2;
            int m = m0 + warp_m * 32 + mf * 16 + trow;
#pragma unroll
            for (int hh = 0; hh < 2; hh++) {
                float v0 = acc[mf][nf][hh * 2];
                float v1 = acc[mf][nf][hh * 2 + 1];
                int mr = m + hh * 8;
                if (EPI == 1) {
                    v0 = softplus_f(v0 + bias[n]);
                    v1 = softplus_f(v1 + bias[n + 1]);
                }
                if (EPI == 3) {
                    if (n < N)     atomicAdd(&C[(size_t)mr * ldc + n], v0);
                    if (n + 1 < N) atomicAdd(&C[(size_t)mr * ldc + n + 1], v1);
                } else {
                    *reinterpret_cast<float2*>(&C[(size_t)mr * ldc + n]) =
                        make_float2(v0, v1);
                }
            }
        }
    }
#undef LOAD_STAGE
}

// ---------------- selective scan: block-staged, 24 ch/CTA, 1 wave ----------
__global__ void __launch_bounds__(SCH * 16) scan_k(
    const float* __restrict__ delta, const float* __restrict__ xc,
    const float* __restrict__ xz, const float* __restrict__ xdbl,
    const float* __restrict__ A_log, const float* __restrict__ dski,
    __nv_bfloat16* __restrict__ ye) {
    // d/u/z tiles [3][buf][TILE][SCH]; B/C tiles [2][buf][TILE][DS]
    __shared__ __align__(16) float sduz[3][2][TILE * SCH];
    __shared__ __align__(16) float sbc[2][2][TILE * DS];
    int tid = threadIdx.x;
    int wid = tid >> 5, lane = tid & 31;
    int half = lane >> 4, s = lane & 15;
    int c0 = blockIdx.x * SCH;
    int b = c0 / DI, d0 = c0 % DI;
    int cib = wid * 2 + half;          // channel-in-block 0..23
    int d = d0 + cib;

    float As = -__expf(A_log[d * DS + s]);
    float dsk = dski[d];

    // loader mapping duz: row = tid/12 (0..31), piece = (tid%12)*8 bytes
    int lrow = tid / 12;
    int lcol = (tid % 12) * 8;
    const char* dbase = (const char*)(delta + (size_t)b * LSZ * DI + d0) + lcol;
    const char* ubase = (const char*)(xc + (size_t)b * LSZ * DI + d0) + lcol;
    const char* zbase = (const char*)(xz + (size_t)b * LSZ * (2 * DI) + DI + d0) + lcol;
    // loader mapping B/C: row2 = tid>>3 (0..31), piece2 = (tid&7)*8, tid<256
    int lrow2 = tid >> 3;
    int lcol2 = (tid & 7) * 8;
    const char* bbase = (const char*)(xdbl + (size_t)b * LSZ * XPN + DTR) + lcol2;
    const char* cbase = bbase + DS * 4;
    uint32_t sduz_u = smem_to_u32(sduz);
    uint32_t sbc_u = smem_to_u32(sbc);
    uint32_t soff = (uint32_t)(lrow * (SCH * 4) + lcol);
    uint32_t soff2 = (uint32_t)(lrow2 * (DS * 4) + lcol2);

#define SCAN_LOAD(buf, t) do { \
    if ((t) < LSZ / TILE) { \
        size_t gl = (size_t)((t) * TILE); \
        cp8(sduz_u + (0 * 2 + (buf)) * (TILE * SCH * 4) + soff, \
            dbase + (gl + lrow) * (DI * 4)); \
        cp8(sduz_u + (1 * 2 + (buf)) * (TILE * SCH * 4) + soff, \
            ubase + (gl + lrow) * (DI * 4)); \
        cp8(sduz_u + (2 * 2 + (buf)) * (TILE * SCH * 4) + soff, \
            zbase + (gl + lrow) * (2 * DI * 4)); \
        if (tid < 256) { \
            cp8(sbc_u + (0 * 2 + (buf)) * (TILE * DS * 4) + soff2, \
                bbase + (gl + lrow2) * (XPN * 4)); \
            cp8(sbc_u + (1 * 2 + (buf)) * (TILE * DS * 4) + soff2, \
                cbase + (gl + lrow2) * (XPN * 4)); \
        } \
    } \
    asm volatile("cp.async.commit_group;"); \
} while (0)

    SCAN_LOAD(0, 0);
    SCAN_LOAD(1, 1);

    float h = 0.f;
    float praw = 0.f, ppart = 0.f;    // raw p (step l-1), partial p (step l-2)
    float u1 = 0.f, z1 = 0.f, u2 = 0.f, z2 = 0.f;
    __nv_bfloat16* yr = ye + (size_t)b * LSZ * KE_BIG + d;

    const int NT = LSZ / TILE;
    for (int t = 0; t < NT; t++) {
        asm volatile("cp.async.wait_group 1;" ::: "memory");
        __syncthreads();
        int buf = t & 1;
        const float* sd = sduz[0][buf];
        const float* suu = sduz[1][buf];
        const float* sz = sduz[2][buf];
        const float* sb = sbc[0][buf];
        const float* sc = sbc[1][buf];
#pragma unroll
        for (int j = 0; j < TILE; j++) {
            int l = t * TILE + j;
            float dl = sd[j * SCH + cib];
            float u  = suu[j * SCH + cib];
            float z  = sz[j * SCH + cib];
            float bm = sb[j * DS + s];
            float cm = sc[j * DS + s];
            float a8 = __shfl_xor_sync(0xffffffffu, praw, 8);
            float b2 = __shfl_xor_sync(0xffffffffu, ppart, 2);
            float dA = __expf(dl * As);
            float dlu = dl * u;
            praw += a8;
            ppart += b2;
            float a4 = __shfl_xor_sync(0xffffffffu, praw, 4);
            float b1 = __shfl_xor_sync(0xffffffffu, ppart, 1);
            h = dA * h + dlu * bm;
            float pnew = h * cm;
            praw += a4;
            ppart += b1;
            if (l >= 2 && s == 0) {
                float yv = (ppart + u2 * dsk) * (z2 / (1.f + __expf(-z2)));
                __nv_bfloat16 hh, ll; bsplit(yv, hh, ll);
                __nv_bfloat16* yp = yr + (size_t)(l - 2) * KE_BIG;
                yp[0] = hh; yp[DI] = hh; yp[2 * DI] = ll;
            }
            ppart = praw; praw = pnew;
            u2 = u1; z2 = z1; u1 = u; z1 = z;
        }
        __syncthreads();
        SCAN_LOAD(buf, t + 2);
    }
    // drain last two steps
    ppart += __shfl_xor_sync(0xffffffffu, ppart, 2);
    ppart += __shfl_xor_sync(0xffffffffu, ppart, 1);
    praw += __shfl_xor_sync(0xffffffffu, praw, 8);
    praw += __shfl_xor_sync(0xffffffffu, praw, 4);
    praw += __shfl_xor_sync(0xffffffffu, praw, 2);
    praw += __shfl_xor_sync(0xffffffffu, praw, 1);
    if (s == 0) {
        float yv = (ppart + u2 * dsk) * (z2 / (1.f + __expf(-z2)));
        __nv_bfloat16 hh, ll; bsplit(yv, hh, ll);
        __nv_bfloat16* yp = yr + (size_t)(LSZ - 2) * KE_BIG;
        yp[0] = hh; yp[DI] = hh; yp[2 * DI] = ll;
        yv = (praw + u1 * dsk) * (z1 / (1.f + __expf(-z1)));
        bsplit(yv, hh, ll);
        yp = yr + (size_t)(LSZ - 1) * KE_BIG;
        yp[0] = hh; yp[DI] = hh; yp[2 * DI] = ll;
    }
#undef SCAN_LOAD
}

// ---------------- final: last-token rmsnorm ----------------
__global__ void final_k(const float* __restrict__ resid, const float* __restrict__ nw,
                        const int* __restrict__ mask, float* __restrict__ out) {
    int b = blockIdx.x;
    float ms = 0.f;
    for (int i = threadIdx.x; i < LSZ; i += blockDim.x) ms += (float)mask[b * LSZ + i];
    ms = block_sum(ms);
    int last = (int)(ms + 0.5f) - 1;
    const float* xr = resid + ((size_t)b * LSZ + last) * DM;
    float sacc = 0.f;
    for (int cidx = threadIdx.x; cidx < DM; cidx += blockDim.x) {
        float v = xr[cidx];
        sacc += v * v;
    }
    sacc = block_sum(sacc);
    float inv = rsqrtf(sacc / (float)DM + 1e-5f);
    for (int cidx = threadIdx.x; cidx < DM; cidx += blockDim.x)
        out[b * DM + cidx] = xr[cidx] * inv * nw[cidx];
}

// ---------------- driver ----------------
extern "C" void kernel_launch(void* const* d_in, const int* in_sizes, int n_in,
                              void* d_out, int out_size) {
    const int*   seq       = (const int*)d_in[0];
    const int*   mask      = (const int*)d_in[1];
    const float* emb       = (const float*)d_in[2];
    const float* norm_w    = (const float*)d_in[3];
    const float* in_proj_w = (const float*)d_in[4];
    const float* conv_w    = (const float*)d_in[5];
    const float* conv_b    = (const float*)d_in[6];
    const float* x_proj_w  = (const float*)d_in[7];
    const float* dt_w      = (const float*)d_in[8];
    const float* dt_b      = (const float*)d_in[9];
    const float* A_log     = (const float*)d_in[10];
    const float* D_skip    = (const float*)d_in[11];
    const float* out_w     = (const float*)d_in[12];
    const float* normf_w   = (const float*)d_in[13];

    float *resid, *xz, *xc, *xdbl, *delta;
    __nv_bfloat16 *ae;
    cudaGetSymbolAddress((void**)&resid, g_resid);
    cudaGetSymbolAddress((void**)&xz,    g_xz);
    cudaGetSymbolAddress((void**)&xc,    g_xc);
    cudaGetSymbolAddress((void**)&xdbl,  g_xdbl);
    cudaGetSymbolAddress((void**)&delta, g_delta);
    cudaGetSymbolAddress((void**)&ae,    g_aext);
    __nv_bfloat16 *wi, *wo, *wx, *wd;
    cudaGetSymbolAddress((void**)&wi, g_wi);
    cudaGetSymbolAddress((void**)&wo, g_wo);
    cudaGetSymbolAddress((void**)&wx, g_wx);
    cudaGetSymbolAddress((void**)&wd, g_wd);

    cudaFuncSetAttribute(gemm_bf<0>, cudaFuncAttributeMaxDynamicSharedMemorySize, GSMEM);
    cudaFuncSetAttribute(gemm_bf<1>, cudaFuncAttributeMaxDynamicSharedMemorySize, GSMEM);
    cudaFuncSetAttribute(gemm_bf<3>, cudaFuncAttributeMaxDynamicSharedMemorySize, GSMEM);
    cudaFuncSetAttribute(gemm_bf<0>, cudaFuncAttributePreferredSharedMemoryCarveout, 100);
    cudaFuncSetAttribute(gemm_bf<1>, cudaFuncAttributePreferredSharedMemoryCarveout, 100);
    cudaFuncSetAttribute(gemm_bf<3>, cudaFuncAttributePreferredSharedMemoryCarveout, 100);

    embed_k<<<(ROWS * (DM / 4) + 255) / 256, 256>>>(seq, emb, resid);

    // ---- all weight-ext preps upfront ----
    for (int i = 0; i < NL; i++) {
        wprep_k<<<(2 * DI * DM / 4 + 255) / 256, 256>>>(
            in_proj_w + (size_t)i * 2 * DI * DM, wi + (size_t)i * (2 * DI) * KE_IN,
            2 * DI, 2 * DI, DM, DM);
        wprep_k<<<(DM * DI / 4 + 255) / 256, 256>>>(
            out_w + (size_t)i * DM * DI, wo + (size_t)i * DM * KE_BIG,
            DM, DM, DI, DI);
        wprep_k<<<(128 * DI / 4 + 255) / 256, 256>>>(
            x_proj_w + (size_t)i * XPN * DI, wx + (size_t)i * 128 * KE_BIG,
            XPN, 128, DI, DI);
        wprep_k<<<(DI * 64 / 4 + 255) / 256, 256>>>(
            dt_w + (size_t)i * DI * DTR, wd + (size_t)i * DI * KE_DT,
            DI, DI, DTR, 64);
    }

    for (int i = 0; i < NL; i++) {
        rmsnorm_k<<<ROWS, 192>>>(resid, norm_w + i * DM, ae);
        // in_proj: xz = hn @ W^T   (N=3072, Kext=2304, 72 iters)
        gemm_bf<0><<<dim3(24, 16, 1), 256, GSMEM>>>(
            ae, wi + (size_t)i * (2 * DI) * KE_IN, xz, nullptr,
            KE_IN, KE_IN / 32, 2 * DI, 2 * DI);

        conv_silu_k<<<(ROWS * DI) / 256, 256>>>(
            xz, conv_w + i * DI * 4, conv_b + i * DI, xc, ae);

        // x_proj: xdbl = xc @ W^T  (N=80 pad 128, Kext=4608, split-K z=16)
        cudaMemsetAsync(xdbl, 0, (size_t)ROWS * XPN * sizeof(float));
        gemm_bf<3><<<dim3(1, 16, 16), 256, GSMEM>>>(
            ae, wx + (size_t)i * 128 * KE_BIG, xdbl, nullptr,
            KE_BIG, KE_BIG / (16 * 32), XPN, XPN);

        // dt: delta = softplus(xdbl[:, :48] @ dt_w^T + dt_b)
        dtprep_k<<<(ROWS * 64 / 4 + 255) / 256, 256>>>(xdbl, ae);
        gemm_bf<1><<<dim3(12, 16, 1), 256, GSMEM>>>(
            ae, wd + (size_t)i * DI * KE_DT, delta, dt_b + i * DI,
            KE_DT, KE_DT / 32, DI, DI);

        // selective scan -> y ext (Kext=4608), 128 CTAs = 1 wave
        scan_k<<<BSZ * DI / SCH, SCH * 16>>>(
            delta, xc, xz, xdbl, A_log + i * DI * DS, D_skip + i * DI, ae);

        // out_proj: resid += y @ W^T  (N=768, Kext=4608, split-K z=3, atomics)
        gemm_bf<3><<<dim3(6, 16, 3), 256, GSMEM>>>(
            ae, wo + (size_t)i * DM * KE_BIG, resid, nullptr,
            KE_BIG, KE_BIG / (3 * 32), DM, DM);
    }

    final_k<<<BSZ, 256>>>(resid, normf_w, mask, (float*)d_out);
}

// round 9
// speedup vs baseline: 2.8546x; 1.0372x over previous
#include <cuda_runtime.h>
#include <cuda_bf16.h>
#include <math.h>
#include <stdint.h>

#define BSZ 2
#define LSZ 1024
#define DM 768
#define NL 4
#define DI 1536
#define DS 16
#define DTR 48
#define XPN 80          // DTR + 2*DS
#define ROWS (BSZ*LSZ)  // 2048

// extended-K sizes (3 segments for bf16-split exact GEMM)
#define KE_IN   (3*DM)     // 2304
#define KE_BIG  (3*DI)     // 4608
#define KE_DT   (3*64)     // 192

#define STAGES 3
#define GSMEM (STAGES*16384)   // 48KB dynamic smem -> 2 CTAs/SM

#define TILE 32            // scan steps per staged tile
#define SCH 24             // scan channels per CTA (128 CTAs total)

// ---------------- scratch (device globals; no allocation allowed) ----------
__device__ float g_resid[ROWS * DM];
__device__ float g_xz[ROWS * 2 * DI];
__device__ float g_xc[ROWS * DI];
__device__ float g_xdbl[ROWS * XPN];
__device__ float g_delta[ROWS * DI];
__device__ __nv_bfloat16 g_aext[ROWS * KE_BIG];          // activation ext (reused)
__device__ __nv_bfloat16 g_wi[NL][(2 * DI) * KE_IN];     // in_proj ext
__device__ __nv_bfloat16 g_wo[NL][DM * KE_BIG];          // out_proj ext
__device__ __nv_bfloat16 g_wx[NL][128 * KE_BIG];         // x_proj ext (N padded 128)
__device__ __nv_bfloat16 g_wd[NL][DI * KE_DT];           // dt ext

// ---------------- small helpers ----------------
__device__ __forceinline__ uint32_t smem_to_u32(const void* p) {
    uint32_t a;
    asm("{ .reg .u64 t; cvta.to.shared.u64 t, %1; cvt.u32.u64 %0, t; }"
        : "=r"(a) : "l"(p));
    return a;
}
__device__ __forceinline__ void cp16(uint32_t dst, const void* src) {
    asm volatile("cp.async.cg.shared.global [%0], [%1], 16;" :: "r"(dst), "l"(src));
}
__device__ __forceinline__ void cp8(uint32_t dst, const void* src) {
    asm volatile("cp.async.ca.shared.global [%0], [%1], 8;" :: "r"(dst), "l"(src));
}
__device__ __forceinline__ void ldsm4(uint32_t* r, uint32_t addr) {
    asm volatile("ldmatrix.sync.aligned.m8n8.x4.shared.b16 {%0,%1,%2,%3}, [%4];"
        : "=r"(r[0]), "=r"(r[1]), "=r"(r[2]), "=r"(r[3]) : "r"(addr));
}
__device__ __forceinline__ void mma16816(float* c, const uint32_t* a, const uint32_t* b) {
    asm volatile("mma.sync.aligned.m16n8k16.row.col.f32.bf16.bf16.f32 "
        "{%0,%1,%2,%3}, {%4,%5,%6,%7}, {%8,%9}, {%0,%1,%2,%3};"
        : "+f"(c[0]), "+f"(c[1]), "+f"(c[2]), "+f"(c[3])
        : "r"(a[0]), "r"(a[1]), "r"(a[2]), "r"(a[3]), "r"(b[0]), "r"(b[1]));
}
__device__ __forceinline__ void bsplit(float v, __nv_bfloat16& h, __nv_bfloat16& l) {
    h = __float2bfloat16(v);
    l = __float2bfloat16(v - __bfloat162float(h));
}
__device__ __forceinline__ float softplus_f(float v) {
    return fmaxf(v, 0.f) + __logf(1.f + __expf(-fabsf(v)));
}

__device__ __forceinline__ float block_sum(float v) {
    __shared__ float sh[8];
    __syncthreads();
#pragma unroll
    for (int o = 16; o; o >>= 1) v += __shfl_xor_sync(0xffffffffu, v, o);
    if ((threadIdx.x & 31) == 0) sh[threadIdx.x >> 5] = v;
    __syncthreads();
    if (threadIdx.x < 32) {
        float t = (threadIdx.x < (blockDim.x >> 5)) ? sh[threadIdx.x] : 0.f;
#pragma unroll
        for (int o = 4; o; o >>= 1) t += __shfl_xor_sync(0xffffffffu, t, o);
        if (threadIdx.x == 0) sh[0] = t;
    }
    __syncthreads();
    return sh[0];
}

// ---------------- embedding gather ----------------
__global__ void embed_k(const int* __restrict__ seq, const float* __restrict__ emb,
                        float* __restrict__ resid) {
    int i = blockIdx.x * blockDim.x + threadIdx.x;
    if (i >= ROWS * (DM / 4)) return;
    int row = i / (DM / 4), c4 = i % (DM / 4);
    int tok = seq[row];
    reinterpret_cast<float4*>(resid)[(size_t)row * (DM / 4) + c4] =
        reinterpret_cast<const float4*>(emb)[(size_t)tok * (DM / 4) + c4];
}

// ---------------- rmsnorm: writes ext layout (Kext=2304) -------------------
__global__ void rmsnorm_k(const float* __restrict__ x, const float* __restrict__ w,
                          __nv_bfloat16* __restrict__ ae) {
    int row = blockIdx.x;
    const float* xr = x + (size_t)row * DM;
    float s = 0.f;
    for (int c = threadIdx.x; c < DM; c += blockDim.x) { float v = xr[c]; s += v * v; }
    s = block_sum(s);
    float inv = rsqrtf(s / (float)DM + 1e-5f);
    __nv_bfloat16* ar = ae + (size_t)row * KE_IN;
    for (int c4 = threadIdx.x * 4; c4 < DM; c4 += blockDim.x * 4) {
        float4 xv = *reinterpret_cast<const float4*>(xr + c4);
        float4 wv = *reinterpret_cast<const float4*>(w + c4);
        union { __nv_bfloat16 b[4]; uint2 u; } hq, lq;
        float vv[4] = {xv.x * wv.x, xv.y * wv.y, xv.z * wv.z, xv.w * wv.w};
#pragma unroll
        for (int j = 0; j < 4; j++) bsplit(vv[j] * inv, hq.b[j], lq.b[j]);
        *reinterpret_cast<uint2*>(ar + c4) = hq.u;
        *reinterpret_cast<uint2*>(ar + DM + c4) = hq.u;
        *reinterpret_cast<uint2*>(ar + 2 * DM + c4) = lq.u;
    }
}

// ---------------- weight prep (vectorized x4) ------------------------------
__global__ void wprep_k(const float* __restrict__ w, __nv_bfloat16* __restrict__ e,
                        int N, int Npad, int Ksrc, int Kpad) {
    int i4 = (blockIdx.x * blockDim.x + threadIdx.x) * 4;
    if (i4 >= Npad * Kpad) return;
    int n = i4 / Kpad, k = i4 - n * Kpad;
    float4 v = make_float4(0.f, 0.f, 0.f, 0.f);
    if (n < N && k < Ksrc)
        v = *reinterpret_cast<const float4*>(w + (size_t)n * Ksrc + k);
    union { __nv_bfloat16 b[4]; uint2 u; } hq, lq;
    bsplit(v.x, hq.b[0], lq.b[0]); bsplit(v.y, hq.b[1], lq.b[1]);
    bsplit(v.z, hq.b[2], lq.b[2]); bsplit(v.w, hq.b[3], lq.b[3]);
    __nv_bfloat16* er = e + (size_t)n * (3 * Kpad);
    *reinterpret_cast<uint2*>(er + k) = hq.u;
    *reinterpret_cast<uint2*>(er + Kpad + k) = lq.u;
    *reinterpret_cast<uint2*>(er + 2 * Kpad + k) = hq.u;
}

// ---------------- dt A prep: xdbl[:, :48] -> ext [ROWS, 192] (x4) ----------
__global__ void dtprep_k(const float* __restrict__ xdbl, __nv_bfloat16* __restrict__ ae) {
    int i4 = (blockIdx.x * blockDim.x + threadIdx.x) * 4;
    if (i4 >= ROWS * 64) return;
    int r = i4 >> 6, k = i4 & 63;
    float4 v = make_float4(0.f, 0.f, 0.f, 0.f);
    if (k < DTR)
        v = *reinterpret_cast<const float4*>(xdbl + (size_t)r * XPN + k);
    union { __nv_bfloat16 b[4]; uint2 u; } hq, lq;
    bsplit(v.x, hq.b[0], lq.b[0]); bsplit(v.y, hq.b[1], lq.b[1]);
    bsplit(v.z, hq.b[2], lq.b[2]); bsplit(v.w, hq.b[3], lq.b[3]);
    __nv_bfloat16* ar = ae + (size_t)r * KE_DT;
    *reinterpret_cast<uint2*>(ar + k) = hq.u;
    *reinterpret_cast<uint2*>(ar + 64 + k) = hq.u;
    *reinterpret_cast<uint2*>(ar + 128 + k) = lq.u;
}

// ---------------- depthwise conv + silu: fp32 + ext (Kext=4608) ------------
__global__ void conv_silu_k(const float* __restrict__ xz, const float* __restrict__ cw,
                            const float* __restrict__ cb, float* __restrict__ xc,
                            __nv_bfloat16* __restrict__ ae) {
    int i = blockIdx.x * blockDim.x + threadIdx.x;
    if (i >= ROWS * DI) return;
    int d = i % DI;
    int row = i / DI;
    int l = row & (LSZ - 1);
    float acc = cb[d];
#pragma unroll
    for (int k = 0; k < 4; k++) {
        int l2 = l + k - 3;
        if (l2 >= 0)
            acc += xz[(size_t)(row + k - 3) * (2 * DI) + d] * cw[d * 4 + k];
    }
    acc = acc / (1.f + __expf(-acc));
    xc[i] = acc;
    __nv_bfloat16 h, lo; bsplit(acc, h, lo);
    __nv_bfloat16* ar = ae + (size_t)row * KE_BIG;
    ar[d] = h; ar[d + DI] = h; ar[d + 2 * DI] = lo;
}

// ---------------- bf16 tensor-core GEMM: C = Aext @ Wext^T -----------------
// CTA tile 128x128x32, 8 warps (4x2), 3-stage cp.async, 2 CTAs/SM.
// EPI: 0 = store, 1 = softplus(acc + bias[n]), 3 = atomicAdd (guard n < N)
template <int EPI>
__global__ void __launch_bounds__(256, 2) gemm_bf(
    const __nv_bfloat16* __restrict__ Aext, const __nv_bfloat16* __restrict__ Wext,
    float* __restrict__ C, const float* __restrict__ bias,
    int Kext, int kIters, int N, int ldc) {
    extern __shared__ __align__(16) uint8_t smem[];
    int tid = threadIdx.x;
    int wid = tid >> 5, lane = tid & 31;
    int m0 = blockIdx.y * 128, n0 = blockIdx.x * 128;
    int kbase = blockIdx.z * kIters * 32;

    int warp_m = wid & 3, warp_n = wid >> 2;   // 4 x 2 warp grid

    int lrow = tid >> 2;       // 0..63
    int lch = tid & 3;         // 0..3
    const char* Ag = (const char*)(Aext + (size_t)(m0 + lrow) * Kext + kbase + lch * 8);
    const char* Bg = (const char*)(Wext + (size_t)(n0 + lrow) * Kext + kbase + lch * 8);
    size_t rstep = (size_t)64 * Kext * 2;
    uint32_t su = smem_to_u32(smem);
    uint32_t dst0 = (uint32_t)(lrow * 64 + ((lch ^ ((lrow >> 1) & 3)) * 16));

    float acc[2][8][4];
#pragma unroll
    for (int a = 0; a < 2; a++)
#pragma unroll
        for (int b = 0; b < 8; b++)
#pragma unroll
            for (int c = 0; c < 4; c++) acc[a][b][c] = 0.f;

#define LOAD_STAGE(st, kt) do { \
    if ((kt) < kIters) { \
        uint32_t _o = (uint32_t)(st) * 16384 + dst0; \
        size_t _g = (size_t)(kt) * 64; \
        cp16(su + _o, Ag + _g); \
        cp16(su + _o + 4096, Ag + rstep + _g); \
        cp16(su + _o + 8192, Bg + _g); \
        cp16(su + _o + 12288, Bg + rstep + _g); \
    } \
    asm volatile("cp.async.commit_group;"); \
} while (0)

    LOAD_STAGE(0, 0);
    LOAD_STAGE(1, 1);

    int cur = 0;
    for (int kt = 0; kt < kIters; kt++) {
        asm volatile("cp.async.wait_group 1;" ::: "memory");
        __syncthreads();
        int nst = cur + 2; if (nst >= STAGES) nst -= STAGES;
        LOAD_STAGE(nst, kt + 2);
        uint32_t baseA = su + cur * 16384;
        uint32_t baseB = baseA + 8192;
#pragma unroll
        for (int ks = 0; ks < 2; ks++) {
            int lr16 = lane & 15;
            int ach = ks * 2 + (lane >> 4);
            uint32_t afr[2][4];
#pragma unroll
            for (int mf = 0; mf < 2; mf++) {
                int r = warp_m * 32 + mf * 16 + lr16;
                ldsm4(afr[mf], baseA + r * 64 + ((ach ^ ((r >> 1) & 3)) * 16));
            }
#pragma unroll
            for (int np = 0; np < 4; np++) {
                int r = warp_n * 64 + np * 16 + lr16;
                uint32_t bfr[4];
                ldsm4(bfr, baseB + r * 64 + ((ach ^ ((r >> 1) & 3)) * 16));
                uint32_t b0[2] = {bfr[0], bfr[2]};
                uint32_t b1[2] = {bfr[1], bfr[3]};
#pragma unroll
                for (int mf = 0; mf < 2; mf++) {
                    mma16816(acc[mf][np * 2], afr[mf], b0);
                    mma16816(acc[mf][np * 2 + 1], afr[mf], b1);
                }
            }
        }
        cur = cur + 1 == STAGES ? 0 : cur + 1;
    }

    int trow = lane >> 2, tc2 = (lane & 3) * 2;
#pragma unroll
    for (int mf = 0; mf < 2; mf++) {
#pragma unroll
        for (int nf = 0; nf < 8; nf++) {
            int n = n0 + warp_n * 64 + nf * 8 + tc2;
            int m = m0 + warp_m * 32 + mf * 16 + trow;
#pragma unroll
            for (int hh = 0; hh < 2; hh++) {
                float v0 = acc[mf][nf][hh * 2];
                float v1 = acc[mf][nf][hh * 2 + 1];
                int mr = m + hh * 8;
                if (EPI == 1) {
                    v0 = softplus_f(v0 + bias[n]);
                    v1 = softplus_f(v1 + bias[n + 1]);
                }
                if (EPI == 3) {
                    if (n < N)     atomicAdd(&C[(size_t)mr * ldc + n], v0);
                    if (n + 1 < N) atomicAdd(&C[(size_t)mr * ldc + n + 1], v1);
                } else {
                    *reinterpret_cast<float2*>(&C[(size_t)mr * ldc + n]) =
                        make_float2(v0, v1);
                }
            }
        }
    }
#undef LOAD_STAGE
}

// ---------------- selective scan: block-staged, smem y staging -------------
__global__ void __launch_bounds__(SCH * 16) scan_k(
    const float* __restrict__ delta, const float* __restrict__ xc,
    const float* __restrict__ xz, const float* __restrict__ xdbl,
    const float* __restrict__ A_log, const float* __restrict__ dski,
    __nv_bfloat16* __restrict__ ye) {
    // d/u/z tiles [3][buf][TILE][SCH]; B/C tiles [2][buf][TILE][DS]
    __shared__ __align__(16) float sduz[3][2][TILE * SCH];
    __shared__ __align__(16) float sbc[2][2][TILE * DS];
    __shared__ __align__(16) float sy[2][TILE][SCH];
    int tid = threadIdx.x;
    int wid = tid >> 5, lane = tid & 31;
    int half = lane >> 4, s = lane & 15;
    int c0 = blockIdx.x * SCH;
    int b = c0 / DI, d0 = c0 % DI;
    int cib = wid * 2 + half;          // channel-in-block 0..23
    int d = d0 + cib;

    float As = -__expf(A_log[d * DS + s]);
    float dsk = dski[d];

    // loader mapping duz: row = tid/12 (0..31), piece = (tid%12)*8 bytes
    int lrow = tid / 12;
    int lcol = (tid % 12) * 8;
    const char* dbase = (const char*)(delta + (size_t)b * LSZ * DI + d0) + lcol;
    const char* ubase = (const char*)(xc + (size_t)b * LSZ * DI + d0) + lcol;
    const char* zbase = (const char*)(xz + (size_t)b * LSZ * (2 * DI) + DI + d0) + lcol;
    // loader mapping B/C: row2 = tid>>3 (0..31), piece2 = (tid&7)*8, tid<256
    int lrow2 = tid >> 3;
    int lcol2 = (tid & 7) * 8;
    const char* bbase = (const char*)(xdbl + (size_t)b * LSZ * XPN + DTR) + lcol2;
    const char* cbase = bbase + DS * 4;
    uint32_t sduz_u = smem_to_u32(sduz);
    uint32_t sbc_u = smem_to_u32(sbc);
    uint32_t soff = (uint32_t)(lrow * (SCH * 4) + lcol);
    uint32_t soff2 = (uint32_t)(lrow2 * (DS * 4) + lcol2);

#define SCAN_LOAD(buf, t) do { \
    if ((t) < LSZ / TILE) { \
        size_t gl = (size_t)((t) * TILE); \
        cp8(sduz_u + (0 * 2 + (buf)) * (TILE * SCH * 4) + soff, \
            dbase + (gl + lrow) * (DI * 4)); \
        cp8(sduz_u + (1 * 2 + (buf)) * (TILE * SCH * 4) + soff, \
            ubase + (gl + lrow) * (DI * 4)); \
        cp8(sduz_u + (2 * 2 + (buf)) * (TILE * SCH * 4) + soff, \
            zbase + (gl + lrow) * (2 * DI * 4)); \
        if (tid < 256) { \
            cp8(sbc_u + (0 * 2 + (buf)) * (TILE * DS * 4) + soff2, \
                bbase + (gl + lrow2) * (XPN * 4)); \
            cp8(sbc_u + (1 * 2 + (buf)) * (TILE * DS * 4) + soff2, \
                cbase + (gl + lrow2) * (XPN * 4)); \
        } \
    } \
    asm volatile("cp.async.commit_group;"); \
} while (0)

// flush one completed y-tile (32 rows x SCH channels) to ext layout
#define Y_FLUSH(yt) do { \
    int bufy = (yt) & 1; \
    for (int f = tid; f < TILE * 3 * 12; f += SCH * 16) { \
        int chunk = f % 12; int rs = f / 12; \
        int seg = rs % 3; int row = rs / 3; \
        int l = (yt) * TILE + row; \
        float v0 = sy[bufy][row][chunk * 2]; \
        float v1 = sy[bufy][row][chunk * 2 + 1]; \
        union { __nv_bfloat16 bb[2]; uint32_t u; } pk; \
        __nv_bfloat16 h0, l0, h1, l1; \
        bsplit(v0, h0, l0); bsplit(v1, h1, l1); \
        pk.bb[0] = (seg == 2) ? l0 : h0; \
        pk.bb[1] = (seg == 2) ? l1 : h1; \
        *reinterpret_cast<uint32_t*>( \
            ye + ((size_t)b * LSZ + l) * KE_BIG + seg * DI + d0 + chunk * 2) = pk.u; \
    } \
} while (0)

    SCAN_LOAD(0, 0);
    SCAN_LOAD(1, 1);

    float h = 0.f;
    float praw = 0.f, ppart = 0.f;    // raw p (step l-1), partial p (step l-2)
    float u1 = 0.f, z1 = 0.f, u2 = 0.f, z2 = 0.f;

    const int NT = LSZ / TILE;
    for (int t = 0; t < NT; t++) {
        asm volatile("cp.async.wait_group 1;" ::: "memory");
        __syncthreads();
        int buf = t & 1;
        const float* sd = sduz[0][buf];
        const float* suu = sduz[1][buf];
        const float* sz = sduz[2][buf];
        const float* sb = sbc[0][buf];
        const float* sc = sbc[1][buf];
#pragma unroll
        for (int j = 0; j < TILE; j++) {
            int l = t * TILE + j;
            float dl = sd[j * SCH + cib];
            float u  = suu[j * SCH + cib];
            float z  = sz[j * SCH + cib];
            float bm = sb[j * DS + s];
            float cm = sc[j * DS + s];
            float a8 = __shfl_xor_sync(0xffffffffu, praw, 8);
            float b2 = __shfl_xor_sync(0xffffffffu, ppart, 2);
            float dA = __expf(dl * As);
            float dlu = dl * u;
            praw += a8;
            ppart += b2;
            float a4 = __shfl_xor_sync(0xffffffffu, praw, 4);
            float b1 = __shfl_xor_sync(0xffffffffu, ppart, 1);
            h = dA * h + dlu * bm;
            float pnew = h * cm;
            praw += a4;
            ppart += b1;
            if (l >= 2 && s == 0) {
                float yv = (ppart + u2 * dsk) * (z2 / (1.f + __expf(-z2)));
                int ly = l - 2;
                sy[(ly >> 5) & 1][ly & 31][cib] = yv;
            }
            ppart = praw; praw = pnew;
            u2 = u1; z2 = z1; u1 = u; z1 = z;
        }
        __syncthreads();
        if (t >= 1) Y_FLUSH(t - 1);
        SCAN_LOAD(buf, t + 2);
    }
    // drain last two steps into sy, then flush final tile
    ppart += __shfl_xor_sync(0xffffffffu, ppart, 2);
    ppart += __shfl_xor_sync(0xffffffffu, ppart, 1);
    praw += __shfl_xor_sync(0xffffffffu, praw, 8);
    praw += __shfl_xor_sync(0xffffffffu, praw, 4);
    praw += __shfl_xor_sync(0xffffffffu, praw, 2);
    praw += __shfl_xor_sync(0xffffffffu, praw, 1);
    if (s == 0) {
        float yv = (ppart + u2 * dsk) * (z2 / (1.f + __expf(-z2)));
        sy[(NT - 1) & 1][TILE - 2][cib] = yv;
        yv = (praw + u1 * dsk) * (z1 / (1.f + __expf(-z1)));
        sy[(NT - 1) & 1][TILE - 1][cib] = yv;
    }
    __syncthreads();
    Y_FLUSH(NT - 1);
#undef SCAN_LOAD
#undef Y_FLUSH
}

// ---------------- final: last-token rmsnorm ----------------
__global__ void final_k(const float* __restrict__ resid, const float* __restrict__ nw,
                        const int* __restrict__ mask, float* __restrict__ out) {
    int b = blockIdx.x;
    float ms = 0.f;
    for (int i = threadIdx.x; i < LSZ; i += blockDim.x) ms += (float)mask[b * LSZ + i];
    ms = block_sum(ms);
    int last = (int)(ms + 0.5f) - 1;
    const float* xr = resid + ((size_t)b * LSZ + last) * DM;
    float sacc = 0.f;
    for (int cidx = threadIdx.x; cidx < DM; cidx += blockDim.x) {
        float v = xr[cidx];
        sacc += v * v;
    }
    sacc = block_sum(sacc);
    float inv = rsqrtf(sacc / (float)DM + 1e-5f);
    for (int cidx = threadIdx.x; cidx < DM; cidx += blockDim.x)
        out[b * DM + cidx] = xr[cidx] * inv * nw[cidx];
}

// ---------------- driver ----------------
extern "C" void kernel_launch(void* const* d_in, const int* in_sizes, int n_in,
                              void* d_out, int out_size) {
    const int*   seq       = (const int*)d_in[0];
    const int*   mask      = (const int*)d_in[1];
    const float* emb       = (const float*)d_in[2];
    const float* norm_w    = (const float*)d_in[3];
    const float* in_proj_w = (const float*)d_in[4];
    const float* conv_w    = (const float*)d_in[5];
    const float* conv_b    = (const float*)d_in[6];
    const float* x_proj_w  = (const float*)d_in[7];
    const float* dt_w      = (const float*)d_in[8];
    const float* dt_b      = (const float*)d_in[9];
    const float* A_log     = (const float*)d_in[10];
    const float* D_skip    = (const float*)d_in[11];
    const float* out_w     = (const float*)d_in[12];
    const float* normf_w   = (const float*)d_in[13];

    float *resid, *xz, *xc, *xdbl, *delta;
    __nv_bfloat16 *ae;
    cudaGetSymbolAddress((void**)&resid, g_resid);
    cudaGetSymbolAddress((void**)&xz,    g_xz);
    cudaGetSymbolAddress((void**)&xc,    g_xc);
    cudaGetSymbolAddress((void**)&xdbl,  g_xdbl);
    cudaGetSymbolAddress((void**)&delta, g_delta);
    cudaGetSymbolAddress((void**)&ae,    g_aext);
    __nv_bfloat16 *wi, *wo, *wx, *wd;
    cudaGetSymbolAddress((void**)&wi, g_wi);
    cudaGetSymbolAddress((void**)&wo, g_wo);
    cudaGetSymbolAddress((void**)&wx, g_wx);
    cudaGetSymbolAddress((void**)&wd, g_wd);

    cudaFuncSetAttribute(gemm_bf<0>, cudaFuncAttributeMaxDynamicSharedMemorySize, GSMEM);
    cudaFuncSetAttribute(gemm_bf<1>, cudaFuncAttributeMaxDynamicSharedMemorySize, GSMEM);
    cudaFuncSetAttribute(gemm_bf<3>, cudaFuncAttributeMaxDynamicSharedMemorySize, GSMEM);
    cudaFuncSetAttribute(gemm_bf<0>, cudaFuncAttributePreferredSharedMemoryCarveout, 100);
    cudaFuncSetAttribute(gemm_bf<1>, cudaFuncAttributePreferredSharedMemoryCarveout, 100);
    cudaFuncSetAttribute(gemm_bf<3>, cudaFuncAttributePreferredSharedMemoryCarveout, 100);

    // launches 1-6 arranged so ncu (-s 5 -c 1) profiles the in_proj GEMM
    embed_k<<<(ROWS * (DM / 4) + 255) / 256, 256>>>(seq, emb, resid);           // 1
    wprep_k<<<(2 * DI * DM / 4 + 255) / 256, 256>>>(
        in_proj_w, wi, 2 * DI, 2 * DI, DM, DM);                                  // 2
    rmsnorm_k<<<ROWS, 192>>>(resid, norm_w, ae);                                 // 3
    wprep_k<<<(128 * DI / 4 + 255) / 256, 256>>>(
        x_proj_w, wx, XPN, 128, DI, DI);                                         // 4
    wprep_k<<<(DI * 64 / 4 + 255) / 256, 256>>>(
        dt_w, wd, DI, DI, DTR, 64);                                              // 5
    gemm_bf<0><<<dim3(24, 16, 1), 256, GSMEM>>>(
        ae, wi, xz, nullptr, KE_IN, KE_IN / 32, 2 * DI, 2 * DI);                 // 6 <- profiled
    wprep_k<<<(DM * DI / 4 + 255) / 256, 256>>>(
        out_w, wo, DM, DM, DI, DI);
    for (int i = 1; i < NL; i++) {
        wprep_k<<<(2 * DI * DM / 4 + 255) / 256, 256>>>(
            in_proj_w + (size_t)i * 2 * DI * DM, wi + (size_t)i * (2 * DI) * KE_IN,
            2 * DI, 2 * DI, DM, DM);
        wprep_k<<<(DM * DI / 4 + 255) / 256, 256>>>(
            out_w + (size_t)i * DM * DI, wo + (size_t)i * DM * KE_BIG,
            DM, DM, DI, DI);
        wprep_k<<<(128 * DI / 4 + 255) / 256, 256>>>(
            x_proj_w + (size_t)i * XPN * DI, wx + (size_t)i * 128 * KE_BIG,
            XPN, 128, DI, DI);
        wprep_k<<<(DI * 64 / 4 + 255) / 256, 256>>>(
            dt_w + (size_t)i * DI * DTR, wd + (size_t)i * DI * KE_DT,
            DI, DI, DTR, 64);
    }

    for (int i = 0; i < NL; i++) {
        if (i > 0) {
            rmsnorm_k<<<ROWS, 192>>>(resid, norm_w + i * DM, ae);
            gemm_bf<0><<<dim3(24, 16, 1), 256, GSMEM>>>(
                ae, wi + (size_t)i * (2 * DI) * KE_IN, xz, nullptr,
                KE_IN, KE_IN / 32, 2 * DI, 2 * DI);
        }

        conv_silu_k<<<(ROWS * DI) / 256, 256>>>(
            xz, conv_w + i * DI * 4, conv_b + i * DI, xc, ae);

        // x_proj: xdbl = xc @ W^T  (N=80 pad 128, Kext=4608, split-K z=16)
        cudaMemsetAsync(xdbl, 0, (size_t)ROWS * XPN * sizeof(float));
        gemm_bf<3><<<dim3(1, 16, 16), 256, GSMEM>>>(
            ae, wx + (size_t)i * 128 * KE_BIG, xdbl, nullptr,
            KE_BIG, KE_BIG / (16 * 32), XPN, XPN);

        // dt: delta = softplus(xdbl[:, :48] @ dt_w^T + dt_b)
        dtprep_k<<<(ROWS * 64 / 4 + 255) / 256, 256>>>(xdbl, ae);
        gemm_bf<1><<<dim3(12, 16, 1), 256, GSMEM>>>(
            ae, wd + (size_t)i * DI * KE_DT, delta, dt_b + i * DI,
            KE_DT, KE_DT / 32, DI, DI);

        // selective scan -> y ext (Kext=4608), 128 CTAs = 1 wave
        scan_k<<<BSZ * DI / SCH, SCH * 16>>>(
            delta, xc, xz, xdbl, A_log + i * DI * DS, D_skip + i * DI, ae);

        // out_proj: resid += y @ W^T  (N=768, Kext=4608, split-K z=3, atomics)
        gemm_bf<3><<<dim3(6, 16, 3), 256, GSMEM>>>(
            ae, wo + (size_t)i * DM * KE_BIG, resid, nullptr,
            KE_BIG, KE_BIG / (3 * 32), DM, DM);
    }

    final_k<<<BSZ, 256>>>(resid, normf_w, mask, (float*)d_out);
}

// round 10
// speedup vs baseline: 2.9004x; 1.0161x over previous
#include <cuda_runtime.h>
#include <cuda_bf16.h>
#include <math.h>
#include <stdint.h>

#define BSZ 2
#define LSZ 1024
#define DM 768
#define NL 4
#define DI 1536
#define DS 16
#define DTR 48
#define XPN 80          // DTR + 2*DS
#define ROWS (BSZ*LSZ)  // 2048

// extended-K sizes (3 segments for bf16-split exact GEMM)
#define KE_IN   (3*DM)     // 2304
#define KE_BIG  (3*DI)     // 4608
#define KE_DT   (3*64)     // 192

#define STAGES 4
#define GSMEM (STAGES*16384)   // 64KB dynamic smem, 2 CTAs/SM (128KB of 228KB)

#define XPZ 16             // x_proj split-K factor

#define TILE 32            // scan steps per staged tile
#define SCH 24             // scan channels per CTA (128 CTAs total)

// ---------------- scratch (device globals; no allocation allowed) ----------
__device__ float g_resid[ROWS * DM];
__device__ float g_xz[ROWS * 2 * DI];
__device__ float g_xc[ROWS * DI];
__device__ float g_xdbl[ROWS * XPN];
__device__ float g_delta[ROWS * DI];
__device__ float g_xpart[XPZ * ROWS * 128];              // x_proj split-K partials
__device__ __nv_bfloat16 g_aext[ROWS * KE_BIG];          // activation ext (reused)
__device__ __nv_bfloat16 g_wi[NL][(2 * DI) * KE_IN];     // in_proj ext
__device__ __nv_bfloat16 g_wo[NL][DM * KE_BIG];          // out_proj ext
__device__ __nv_bfloat16 g_wx[NL][128 * KE_BIG];         // x_proj ext (N padded 128)
__device__ __nv_bfloat16 g_wd[NL][DI * KE_DT];           // dt ext

// ---------------- small helpers ----------------
__device__ __forceinline__ uint32_t smem_to_u32(const void* p) {
    uint32_t a;
    asm("{ .reg .u64 t; cvta.to.shared.u64 t, %1; cvt.u32.u64 %0, t; }"
        : "=r"(a) : "l"(p));
    return a;
}
__device__ __forceinline__ void cp16(uint32_t dst, const void* src) {
    asm volatile("cp.async.cg.shared.global [%0], [%1], 16;" :: "r"(dst), "l"(src));
}
__device__ __forceinline__ void cp8(uint32_t dst, const void* src) {
    asm volatile("cp.async.ca.shared.global [%0], [%1], 8;" :: "r"(dst), "l"(src));
}
__device__ __forceinline__ void ldsm4(uint32_t* r, uint32_t addr) {
    asm volatile("ldmatrix.sync.aligned.m8n8.x4.shared.b16 {%0,%1,%2,%3}, [%4];"
        : "=r"(r[0]), "=r"(r[1]), "=r"(r[2]), "=r"(r[3]) : "r"(addr));
}
__device__ __forceinline__ void mma16816(float* c, const uint32_t* a, const uint32_t* b) {
    asm volatile("mma.sync.aligned.m16n8k16.row.col.f32.bf16.bf16.f32 "
        "{%0,%1,%2,%3}, {%4,%5,%6,%7}, {%8,%9}, {%0,%1,%2,%3};"
        : "+f"(c[0]), "+f"(c[1]), "+f"(c[2]), "+f"(c[3])
        : "r"(a[0]), "r"(a[1]), "r"(a[2]), "r"(a[3]), "r"(b[0]), "r"(b[1]));
}
__device__ __forceinline__ void bsplit(float v, __nv_bfloat16& h, __nv_bfloat16& l) {
    h = __float2bfloat16(v);
    l = __float2bfloat16(v - __bfloat162float(h));
}
__device__ __forceinline__ float softplus_f(float v) {
    return fmaxf(v, 0.f) + __logf(1.f + __expf(-fabsf(v)));
}

__device__ __forceinline__ float block_sum(float v) {
    __shared__ float sh[8];
    __syncthreads();
#pragma unroll
    for (int o = 16; o; o >>= 1) v += __shfl_xor_sync(0xffffffffu, v, o);
    if ((threadIdx.x & 31) == 0) sh[threadIdx.x >> 5] = v;
    __syncthreads();
    if (threadIdx.x < 32) {
        float t = (threadIdx.x < (blockDim.x >> 5)) ? sh[threadIdx.x] : 0.f;
#pragma unroll
        for (int o = 4; o; o >>= 1) t += __shfl_xor_sync(0xffffffffu, t, o);
        if (threadIdx.x == 0) sh[0] = t;
    }
    __syncthreads();
    return sh[0];
}

// ---------------- embedding gather ----------------
__global__ void embed_k(const int* __restrict__ seq, const float* __restrict__ emb,
                        float* __restrict__ resid) {
    int i = blockIdx.x * blockDim.x + threadIdx.x;
    if (i >= ROWS * (DM / 4)) return;
    int row = i / (DM / 4), c4 = i % (DM / 4);
    int tok = seq[row];
    reinterpret_cast<float4*>(resid)[(size_t)row * (DM / 4) + c4] =
        reinterpret_cast<const float4*>(emb)[(size_t)tok * (DM / 4) + c4];
}

// ---------------- rmsnorm: writes ext layout (Kext=2304) -------------------
__global__ void rmsnorm_k(const float* __restrict__ x, const float* __restrict__ w,
                          __nv_bfloat16* __restrict__ ae) {
    int row = blockIdx.x;
    const float* xr = x + (size_t)row * DM;
    float s = 0.f;
    for (int c = threadIdx.x; c < DM; c += blockDim.x) { float v = xr[c]; s += v * v; }
    s = block_sum(s);
    float inv = rsqrtf(s / (float)DM + 1e-5f);
    __nv_bfloat16* ar = ae + (size_t)row * KE_IN;
    for (int c4 = threadIdx.x * 4; c4 < DM; c4 += blockDim.x * 4) {
        float4 xv = *reinterpret_cast<const float4*>(xr + c4);
        float4 wv = *reinterpret_cast<const float4*>(w + c4);
        union { __nv_bfloat16 b[4]; uint2 u; } hq, lq;
        float vv[4] = {xv.x * wv.x, xv.y * wv.y, xv.z * wv.z, xv.w * wv.w};
#pragma unroll
        for (int j = 0; j < 4; j++) bsplit(vv[j] * inv, hq.b[j], lq.b[j]);
        *reinterpret_cast<uint2*>(ar + c4) = hq.u;
        *reinterpret_cast<uint2*>(ar + DM + c4) = hq.u;
        *reinterpret_cast<uint2*>(ar + 2 * DM + c4) = lq.u;
    }
}

// ---------------- weight prep (vectorized x4, batched over layers) ---------
__global__ void wprep_k(const float* __restrict__ w, __nv_bfloat16* __restrict__ e,
                        int N, int Npad, int Ksrc, int Kpad,
                        size_t wstride, size_t estride) {
    int i4 = (blockIdx.x * blockDim.x + threadIdx.x) * 4;
    if (i4 >= Npad * Kpad) return;
    w += (size_t)blockIdx.y * wstride;
    e += (size_t)blockIdx.y * estride;
    int n = i4 / Kpad, k = i4 - n * Kpad;
    float4 v = make_float4(0.f, 0.f, 0.f, 0.f);
    if (n < N && k < Ksrc)
        v = *reinterpret_cast<const float4*>(w + (size_t)n * Ksrc + k);
    union { __nv_bfloat16 b[4]; uint2 u; } hq, lq;
    bsplit(v.x, hq.b[0], lq.b[0]); bsplit(v.y, hq.b[1], lq.b[1]);
    bsplit(v.z, hq.b[2], lq.b[2]); bsplit(v.w, hq.b[3], lq.b[3]);
    __nv_bfloat16* er = e + (size_t)n * (3 * Kpad);
    *reinterpret_cast<uint2*>(er + k) = hq.u;
    *reinterpret_cast<uint2*>(er + Kpad + k) = lq.u;
    *reinterpret_cast<uint2*>(er + 2 * Kpad + k) = hq.u;
}

// ---------------- x_proj reduce: partials -> xdbl + dt-ext -----------------
__global__ void reduce_xp_k(const float* __restrict__ xp, float* __restrict__ xdbl,
                            __nv_bfloat16* __restrict__ ae) {
    int i = blockIdx.x * blockDim.x + threadIdx.x;
    if (i >= ROWS * XPN) return;
    int r = i / XPN, k = i - r * XPN;
    float v = 0.f;
#pragma unroll
    for (int z = 0; z < XPZ; z++)
        v += xp[(size_t)z * ROWS * 128 + (size_t)r * 128 + k];
    xdbl[(size_t)r * XPN + k] = v;
    if (k < 64) {
        float dv = (k < DTR) ? v : 0.f;
        __nv_bfloat16 h, l; bsplit(dv, h, l);
        __nv_bfloat16* ar = ae + (size_t)r * KE_DT;
        ar[k] = h; ar[k + 64] = h; ar[k + 128] = l;
    }
}

// ---------------- depthwise conv + silu: fp32 + ext (Kext=4608) ------------
__global__ void conv_silu_k(const float* __restrict__ xz, const float* __restrict__ cw,
                            const float* __restrict__ cb, float* __restrict__ xc,
                            __nv_bfloat16* __restrict__ ae) {
    int i = blockIdx.x * blockDim.x + threadIdx.x;
    if (i >= ROWS * DI) return;
    int d = i % DI;
    int row = i / DI;
    int l = row & (LSZ - 1);
    float acc = cb[d];
#pragma unroll
    for (int k = 0; k < 4; k++) {
        int l2 = l + k - 3;
        if (l2 >= 0)
            acc += xz[(size_t)(row + k - 3) * (2 * DI) + d] * cw[d * 4 + k];
    }
    acc = acc / (1.f + __expf(-acc));
    xc[i] = acc;
    __nv_bfloat16 h, lo; bsplit(acc, h, lo);
    __nv_bfloat16* ar = ae + (size_t)row * KE_BIG;
    ar[d] = h; ar[d + DI] = h; ar[d + 2 * DI] = lo;
}

// ---------------- bf16 tensor-core GEMM: C = Aext @ Wext^T -----------------
// CTA tile 128x128x32, 8 warps (4x2), 4-stage cp.async, 2 CTAs/SM.
// EPI: 0 = store, 1 = softplus(acc + bias[n]), 3 = atomicAdd (guard n < N),
//      4 = store to per-z partial buffer (C + blockIdx.z * zstride)
template <int EPI>
__global__ void __launch_bounds__(256, 2) gemm_bf(
    const __nv_bfloat16* __restrict__ Aext, const __nv_bfloat16* __restrict__ Wext,
    float* __restrict__ C, const float* __restrict__ bias,
    int Kext, int kIters, int N, int ldc, size_t zstride) {
    extern __shared__ __align__(16) uint8_t smem[];
    int tid = threadIdx.x;
    int wid = tid >> 5, lane = tid & 31;
    int m0 = blockIdx.y * 128, n0 = blockIdx.x * 128;
    int kbase = blockIdx.z * kIters * 32;

    int warp_m = wid & 3, warp_n = wid >> 2;   // 4 x 2 warp grid

    int lrow = tid >> 2;       // 0..63
    int lch = tid & 3;         // 0..3
    const char* Ag = (const char*)(Aext + (size_t)(m0 + lrow) * Kext + kbase + lch * 8);
    const char* Bg = (const char*)(Wext + (size_t)(n0 + lrow) * Kext + kbase + lch * 8);
    size_t rstep = (size_t)64 * Kext * 2;
    uint32_t su = smem_to_u32(smem);
    uint32_t dst0 = (uint32_t)(lrow * 64 + ((lch ^ ((lrow >> 1) & 3)) * 16));

    float acc[2][8][4];
#pragma unroll
    for (int a = 0; a < 2; a++)
#pragma unroll
        for (int b = 0; b < 8; b++)
#pragma unroll
            for (int c = 0; c < 4; c++) acc[a][b][c] = 0.f;

#define LOAD_STAGE(st, kt) do { \
    if ((kt) < kIters) { \
        uint32_t _o = (uint32_t)(st) * 16384 + dst0; \
        size_t _g = (size_t)(kt) * 64; \
        cp16(su + _o, Ag + _g); \
        cp16(su + _o + 4096, Ag + rstep + _g); \
        cp16(su + _o + 8192, Bg + _g); \
        cp16(su + _o + 12288, Bg + rstep + _g); \
    } \
    asm volatile("cp.async.commit_group;"); \
} while (0)

    LOAD_STAGE(0, 0);
    LOAD_STAGE(1, 1);
    LOAD_STAGE(2, 2);

    int cur = 0;
    for (int kt = 0; kt < kIters; kt++) {
        asm volatile("cp.async.wait_group 2;" ::: "memory");
        __syncthreads();
        LOAD_STAGE((cur + 3) & 3, kt + 3);
        uint32_t baseA = su + cur * 16384;
        uint32_t baseB = baseA + 8192;
#pragma unroll
        for (int ks = 0; ks < 2; ks++) {
            int lr16 = lane & 15;
            int ach = ks * 2 + (lane >> 4);
            uint32_t afr[2][4];
#pragma unroll
            for (int mf = 0; mf < 2; mf++) {
                int r = warp_m * 32 + mf * 16 + lr16;
                ldsm4(afr[mf], baseA + r * 64 + ((ach ^ ((r >> 1) & 3)) * 16));
            }
#pragma unroll
            for (int np = 0; np < 4; np++) {
                int r = warp_n * 64 + np * 16 + lr16;
                uint32_t bfr[4];
                ldsm4(bfr, baseB + r * 64 + ((ach ^ ((r >> 1) & 3)) * 16));
                uint32_t b0[2] = {bfr[0], bfr[2]};
                uint32_t b1[2] = {bfr[1], bfr[3]};
#pragma unroll
                for (int mf = 0; mf < 2; mf++) {
                    mma16816(acc[mf][np * 2], afr[mf], b0);
                    mma16816(acc[mf][np * 2 + 1], afr[mf], b1);
                }
            }
        }
        cur = (cur + 1) & 3;
    }

    float* Cz = (EPI == 4) ? C + (size_t)blockIdx.z * zstride : C;
    int trow = lane >> 2, tc2 = (lane & 3) * 2;
#pragma unroll
    for (int mf = 0; mf < 2; mf++) {
#pragma unroll
        for (int nf = 0; nf < 8; nf++) {
            int n = n0 + warp_n * 64 + nf * 8 + tc2;
            int m = m0 + warp_m * 32 + mf * 16 + trow;
#pragma unroll
            for (int hh = 0; hh < 2; hh++) {
                float v0 = acc[mf][nf][hh * 2];
                float v1 = acc[mf][nf][hh * 2 + 1];
                int mr = m + hh * 8;
                if (EPI == 1) {
                    v0 = softplus_f(v0 + bias[n]);
                    v1 = softplus_f(v1 + bias[n + 1]);
                }
                if (EPI == 3) {
                    if (n < N)     atomicAdd(&Cz[(size_t)mr * ldc + n], v0);
                    if (n + 1 < N) atomicAdd(&Cz[(size_t)mr * ldc + n + 1], v1);
                } else {
                    *reinterpret_cast<float2*>(&Cz[(size_t)mr * ldc + n]) =
                        make_float2(v0, v1);
                }
            }
        }
    }
#undef LOAD_STAGE
}

// ---------------- selective scan: block-staged, smem y staging -------------
__global__ void __launch_bounds__(SCH * 16) scan_k(
    const float* __restrict__ delta, const float* __restrict__ xc,
    const float* __restrict__ xz, const float* __restrict__ xdbl,
    const float* __restrict__ A_log, const float* __restrict__ dski,
    __nv_bfloat16* __restrict__ ye) {
    __shared__ __align__(16) float sduz[3][2][TILE * SCH];
    __shared__ __align__(16) float sbc[2][2][TILE * DS];
    __shared__ __align__(16) float sy[2][TILE][SCH];
    int tid = threadIdx.x;
    int wid = tid >> 5, lane = tid & 31;
    int half = lane >> 4, s = lane & 15;
    int c0 = blockIdx.x * SCH;
    int b = c0 / DI, d0 = c0 % DI;
    int cib = wid * 2 + half;          // channel-in-block 0..23
    int d = d0 + cib;

    float As = -__expf(A_log[d * DS + s]);
    float dsk = dski[d];

    int lrow = tid / 12;
    int lcol = (tid % 12) * 8;
    const char* dbase = (const char*)(delta + (size_t)b * LSZ * DI + d0) + lcol;
    const char* ubase = (const char*)(xc + (size_t)b * LSZ * DI + d0) + lcol;
    const char* zbase = (const char*)(xz + (size_t)b * LSZ * (2 * DI) + DI + d0) + lcol;
    int lrow2 = tid >> 3;
    int lcol2 = (tid & 7) * 8;
    const char* bbase = (const char*)(xdbl + (size_t)b * LSZ * XPN + DTR) + lcol2;
    const char* cbase = bbase + DS * 4;
    uint32_t sduz_u = smem_to_u32(sduz);
    uint32_t sbc_u = smem_to_u32(sbc);
    uint32_t soff = (uint32_t)(lrow * (SCH * 4) + lcol);
    uint32_t soff2 = (uint32_t)(lrow2 * (DS * 4) + lcol2);

#define SCAN_LOAD(buf, t) do { \
    if ((t) < LSZ / TILE) { \
        size_t gl = (size_t)((t) * TILE); \
        cp8(sduz_u + (0 * 2 + (buf)) * (TILE * SCH * 4) + soff, \
            dbase + (gl + lrow) * (DI * 4)); \
        cp8(sduz_u + (1 * 2 + (buf)) * (TILE * SCH * 4) + soff, \
            ubase + (gl + lrow) * (DI * 4)); \
        cp8(sduz_u + (2 * 2 + (buf)) * (TILE * SCH * 4) + soff, \
            zbase + (gl + lrow) * (2 * DI * 4)); \
        if (tid < 256) { \
            cp8(sbc_u + (0 * 2 + (buf)) * (TILE * DS * 4) + soff2, \
                bbase + (gl + lrow2) * (XPN * 4)); \
            cp8(sbc_u + (1 * 2 + (buf)) * (TILE * DS * 4) + soff2, \
                cbase + (gl + lrow2) * (XPN * 4)); \
        } \
    } \
    asm volatile("cp.async.commit_group;"); \
} while (0)

#define Y_FLUSH(yt) do { \
    int bufy = (yt) & 1; \
    for (int f = tid; f < TILE * 3 * 12; f += SCH * 16) { \
        int chunk = f % 12; int rs = f / 12; \
        int seg = rs % 3; int row = rs / 3; \
        int l = (yt) * TILE + row; \
        float v0 = sy[bufy][row][chunk * 2]; \
        float v1 = sy[bufy][row][chunk * 2 + 1]; \
        union { __nv_bfloat16 bb[2]; uint32_t u; } pk; \
        __nv_bfloat16 h0, l0, h1, l1; \
        bsplit(v0, h0, l0); bsplit(v1, h1, l1); \
        pk.bb[0] = (seg == 2) ? l0 : h0; \
        pk.bb[1] = (seg == 2) ? l1 : h1; \
        *reinterpret_cast<uint32_t*>( \
            ye + ((size_t)b * LSZ + l) * KE_BIG + seg * DI + d0 + chunk * 2) = pk.u; \
    } \
} while (0)

    SCAN_LOAD(0, 0);
    SCAN_LOAD(1, 1);

    float h = 0.f;
    float praw = 0.f, ppart = 0.f;
    float u1 = 0.f, z1 = 0.f, u2 = 0.f, z2 = 0.f;

    const int NT = LSZ / TILE;
    for (int t = 0; t < NT; t++) {
        asm volatile("cp.async.wait_group 1;" ::: "memory");
        __syncthreads();
        int buf = t & 1;
        const float* sd = sduz[0][buf];
        const float* suu = sduz[1][buf];
        const float* sz = sduz[2][buf];
        const float* sb = sbc[0][buf];
        const float* sc = sbc[1][buf];
#pragma unroll
        for (int j = 0; j < TILE; j++) {
            int l = t * TILE + j;
            float dl = sd[j * SCH + cib];
            float u  = suu[j * SCH + cib];
            float z  = sz[j * SCH + cib];
            float bm = sb[j * DS + s];
            float cm = sc[j * DS + s];
            float a8 = __shfl_xor_sync(0xffffffffu, praw, 8);
            float b2 = __shfl_xor_sync(0xffffffffu, ppart, 2);
            float dA = __expf(dl * As);
            float dlu = dl * u;
            praw += a8;
            ppart += b2;
            float a4 = __shfl_xor_sync(0xffffffffu, praw, 4);
            float b1 = __shfl_xor_sync(0xffffffffu, ppart, 1);
            h = dA * h + dlu * bm;
            float pnew = h * cm;
            praw += a4;
            ppart += b1;
            if (l >= 2 && s == 0) {
                float yv = (ppart + u2 * dsk) * (z2 / (1.f + __expf(-z2)));
                int ly = l - 2;
                sy[(ly >> 5) & 1][ly & 31][cib] = yv;
            }
            ppart = praw; praw = pnew;
            u2 = u1; z2 = z1; u1 = u; z1 = z;
        }
        __syncthreads();
        if (t >= 1) Y_FLUSH(t - 1);
        SCAN_LOAD(buf, t + 2);
    }
    ppart += __shfl_xor_sync(0xffffffffu, ppart, 2);
    ppart += __shfl_xor_sync(0xffffffffu, ppart, 1);
    praw += __shfl_xor_sync(0xffffffffu, praw, 8);
    praw += __shfl_xor_sync(0xffffffffu, praw, 4);
    praw += __shfl_xor_sync(0xffffffffu, praw, 2);
    praw += __shfl_xor_sync(0xffffffffu, praw, 1);
    if (s == 0) {
        float yv = (ppart + u2 * dsk) * (z2 / (1.f + __expf(-z2)));
        sy[(NT - 1) & 1][TILE - 2][cib] = yv;
        yv = (praw + u1 * dsk) * (z1 / (1.f + __expf(-z1)));
        sy[(NT - 1) & 1][TILE - 1][cib] = yv;
    }
    __syncthreads();
    Y_FLUSH(NT - 1);
#undef SCAN_LOAD
#undef Y_FLUSH
}

// ---------------- final: last-token rmsnorm ----------------
__global__ void final_k(const float* __restrict__ resid, const float* __restrict__ nw,
                        const int* __restrict__ mask, float* __restrict__ out) {
    int b = blockIdx.x;
    float ms = 0.f;
    for (int i = threadIdx.x; i < LSZ; i += blockDim.x) ms += (float)mask[b * LSZ + i];
    ms = block_sum(ms);
    int last = (int)(ms + 0.5f) - 1;
    const float* xr = resid + ((size_t)b * LSZ + last) * DM;
    float sacc = 0.f;
    for (int cidx = threadIdx.x; cidx < DM; cidx += blockDim.x) {
        float v = xr[cidx];
        sacc += v * v;
    }
    sacc = block_sum(sacc);
    float inv = rsqrtf(sacc / (float)DM + 1e-5f);
    for (int cidx = threadIdx.x; cidx < DM; cidx += blockDim.x)
        out[b * DM + cidx] = xr[cidx] * inv * nw[cidx];
}

// ---------------- driver ----------------
extern "C" void kernel_launch(void* const* d_in, const int* in_sizes, int n_in,
                              void* d_out, int out_size) {
    const int*   seq       = (const int*)d_in[0];
    const int*   mask      = (const int*)d_in[1];
    const float* emb       = (const float*)d_in[2];
    const float* norm_w    = (const float*)d_in[3];
    const float* in_proj_w = (const float*)d_in[4];
    const float* conv_w    = (const float*)d_in[5];
    const float* conv_b    = (const float*)d_in[6];
    const float* x_proj_w  = (const float*)d_in[7];
    const float* dt_w      = (const float*)d_in[8];
    const float* dt_b      = (const float*)d_in[9];
    const float* A_log     = (const float*)d_in[10];
    const float* D_skip    = (const float*)d_in[11];
    const float* out_w     = (const float*)d_in[12];
    const float* normf_w   = (const float*)d_in[13];

    float *resid, *xz, *xc, *xdbl, *delta, *xpart;
    __nv_bfloat16 *ae;
    cudaGetSymbolAddress((void**)&resid, g_resid);
    cudaGetSymbolAddress((void**)&xz,    g_xz);
    cudaGetSymbolAddress((void**)&xc,    g_xc);
    cudaGetSymbolAddress((void**)&xdbl,  g_xdbl);
    cudaGetSymbolAddress((void**)&delta, g_delta);
    cudaGetSymbolAddress((void**)&xpart, g_xpart);
    cudaGetSymbolAddress((void**)&ae,    g_aext);
    __nv_bfloat16 *wi, *wo, *wx, *wd;
    cudaGetSymbolAddress((void**)&wi, g_wi);
    cudaGetSymbolAddress((void**)&wo, g_wo);
    cudaGetSymbolAddress((void**)&wx, g_wx);
    cudaGetSymbolAddress((void**)&wd, g_wd);

    cudaFuncSetAttribute(gemm_bf<0>, cudaFuncAttributeMaxDynamicSharedMemorySize, GSMEM);
    cudaFuncSetAttribute(gemm_bf<1>, cudaFuncAttributeMaxDynamicSharedMemorySize, GSMEM);
    cudaFuncSetAttribute(gemm_bf<3>, cudaFuncAttributeMaxDynamicSharedMemorySize, GSMEM);
    cudaFuncSetAttribute(gemm_bf<4>, cudaFuncAttributeMaxDynamicSharedMemorySize, GSMEM);
    cudaFuncSetAttribute(gemm_bf<0>, cudaFuncAttributePreferredSharedMemoryCarveout, 100);
    cudaFuncSetAttribute(gemm_bf<1>, cudaFuncAttributePreferredSharedMemoryCarveout, 100);
    cudaFuncSetAttribute(gemm_bf<3>, cudaFuncAttributePreferredSharedMemoryCarveout, 100);
    cudaFuncSetAttribute(gemm_bf<4>, cudaFuncAttributePreferredSharedMemoryCarveout, 100);

    // launches arranged so ncu (-s 5 -c 1) profiles the in_proj GEMM (#6)
    embed_k<<<(ROWS * (DM / 4) + 255) / 256, 256>>>(seq, emb, resid);            // 1
    wprep_k<<<dim3((2 * DI * DM / 4 + 255) / 256, NL), 256>>>(
        in_proj_w, wi, 2 * DI, 2 * DI, DM, DM,
        (size_t)2 * DI * DM, (size_t)(2 * DI) * KE_IN);                          // 2
    wprep_k<<<dim3((128 * DI / 4 + 255) / 256, NL), 256>>>(
        x_proj_w, wx, XPN, 128, DI, DI,
        (size_t)XPN * DI, (size_t)128 * KE_BIG);                                 // 3
    wprep_k<<<dim3((DI * 64 / 4 + 255) / 256, NL), 256>>>(
        dt_w, wd, DI, DI, DTR, 64,
        (size_t)DI * DTR, (size_t)DI * KE_DT);                                   // 4
    rmsnorm_k<<<ROWS, 192>>>(resid, norm_w, ae);                                 // 5
    gemm_bf<0><<<dim3(24, 16, 1), 256, GSMEM>>>(
        ae, wi, xz, nullptr, KE_IN, KE_IN / 32, 2 * DI, 2 * DI, 0);              // 6 <- profiled
    wprep_k<<<dim3((DM * DI / 4 + 255) / 256, NL), 256>>>(
        out_w, wo, DM, DM, DI, DI,
        (size_t)DM * DI, (size_t)DM * KE_BIG);                                   // 7

    for (int i = 0; i < NL; i++) {
        if (i > 0) {
            rmsnorm_k<<<ROWS, 192>>>(resid, norm_w + i * DM, ae);
            gemm_bf<0><<<dim3(24, 16, 1), 256, GSMEM>>>(
                ae, wi + (size_t)i * (2 * DI) * KE_IN, xz, nullptr,
                KE_IN, KE_IN / 32, 2 * DI, 2 * DI, 0);
        }

        conv_silu_k<<<(ROWS * DI) / 256, 256>>>(
            xz, conv_w + i * DI * 4, conv_b + i * DI, xc, ae);

        // x_proj: partials = xc @ W^T  (N pad 128, Kext=4608, split-K z=16)
        gemm_bf<4><<<dim3(1, 16, XPZ), 256, GSMEM>>>(
            ae, wx + (size_t)i * 128 * KE_BIG, xpart, nullptr,
            KE_BIG, KE_BIG / (XPZ * 32), 128, 128, (size_t)ROWS * 128);

        // reduce partials -> xdbl fp32 + dt-ext operand (absorbs dtprep)
        reduce_xp_k<<<(ROWS * XPN + 255) / 256, 256>>>(xpart, xdbl, ae);

        // dt: delta = softplus(xdbl[:, :48] @ dt_w^T + dt_b)
        gemm_bf<1><<<dim3(12, 16, 1), 256, GSMEM>>>(
            ae, wd + (size_t)i * DI * KE_DT, delta, dt_b + i * DI,
            KE_DT, KE_DT / 32, DI, DI, 0);

        // selective scan -> y ext (Kext=4608), 128 CTAs = 1 wave
        scan_k<<<BSZ * DI / SCH, SCH * 16>>>(
            delta, xc, xz, xdbl, A_log + i * DI * DS, D_skip + i * DI, ae);

        // out_proj: resid += y @ W^T  (N=768, Kext=4608, split-K z=3, atomics)
        gemm_bf<3><<<dim3(6, 16, 3), 256, GSMEM>>>(
            ae, wo + (size_t)i * DM * KE_BIG, resid, nullptr,
            KE_BIG, KE_BIG / (3 * 32), DM, DM, 0);
    }

    final_k<<<BSZ, 256>>>(resid, normf_w, mask, (float*)d_out);
}